// round 13
// baseline (speedup 1.0000x reference)
#include <cuda_runtime.h>
#include <cuda_bf16.h>
#include <cstddef>

#define LEAK 0.2f
#define BS 4
#define NSTK 32
#define NPNT 256
#define NPT 8192           // NSTK*NPNT
#define CIN 96
#define SPIN 64
#define DNIN 32
#define MIDDN 110
#define DNOUT 64
#define MIDSP 156
#define SPOUT 128
#define KDN 50
#define SAMPLE_N 512
#define SAMPLE_K 16

typedef unsigned long long ull;

// ---------------- scratch (allocation-free rule: __device__ globals) ----------------
__device__ float g_xt[(size_t)BS * NPT * CIN];       // point-major fused dense features
__device__ float g_x2[BS * NPT];
__device__ unsigned g_D[(size_t)BS * NPT * NPT];     // 1 GiB ORDERING KEYS (okey of distance)
__device__ int   g_knn[(size_t)BS * NPT * KDN];
__device__ float g_A[(size_t)BS * NPT * MIDDN];      // x @ W1a^T
__device__ float g_B[(size_t)BS * NPT * MIDDN];      // x @ (W1b-W1a)^T + b1
__device__ float g_dnfeat[(size_t)BS * DNOUT * NPT]; // channel-major GCN output
__device__ float g_xs[BS * NSTK * CIN];              // fused sparse features, point-major

__device__ __forceinline__ float lrelu(float v) { return v > 0.f ? v : LEAK * v; }

// packed f32x2 helpers (FFMA2: full-rate fp32 on sm_103a; plain FFMA is half-rate)
__device__ __forceinline__ ull dup2(float x) { ull r; asm("mov.b64 %0,{%1,%1};" : "=l"(r) : "f"(x)); return r; }
__device__ __forceinline__ void ffma2(ull& d, ull a, ull b) {
    asm("fma.rn.f32x2 %0,%1,%2,%0;" : "+l"(d) : "l"(a), "l"(b));
}
__device__ __forceinline__ float2 unpk2(ull v) { float2 f; asm("mov.b64 {%0,%1},%2;" : "=f"(f.x), "=f"(f.y) : "l"(v)); return f; }

__device__ __forceinline__ unsigned okey(float d) {
    unsigned u = __float_as_uint(d);
    return (u & 0x80000000u) ? ~u : (u | 0x80000000u);
}

// ---------------- build fused dense features + squared norms ----------------
__global__ void k_build_xt(const float* __restrict__ dense, const float* __restrict__ sparse) {
    int bn = blockIdx.x;            // b*NPT + n
    int b = bn >> 13, n = bn & (NPT - 1);
    int s = n >> 8, p = n & 255;
    int t = threadIdx.x;            // 96
    float v;
    if (t < DNIN) v = dense[(((size_t)(b * DNIN + t) * NSTK + s) << 8) + p];
    else          v = sparse[(b * SPIN + (t - DNIN)) * NSTK + s];
    g_xt[(size_t)bn * CIN + t] = v;
    __shared__ float red[CIN];
    red[t] = v * v;
    __syncthreads();
    if (t < 32) {
        float s2 = red[t] + red[t + 32] + red[t + 64];
        for (int o = 16; o > 0; o >>= 1) s2 += __shfl_down_sync(0xffffffffu, s2, o);
        if (t == 0) g_x2[bn] = s2;
    }
}

// ---------------- sparse fused features ----------------
__global__ void k_spdn(const float* __restrict__ dense) {
    int idx = blockIdx.x;           // (b, c, s)
    int b = idx >> 10, c = (idx >> 5) & 31, s = idx & 31;
    int t = threadIdx.x;            // 256
    float v = dense[(((size_t)(b * DNIN + c) * NSTK + s) << 8) + t];
    __shared__ float red[256];
    red[t] = v;
    __syncthreads();
    for (int o = 128; o >= 32; o >>= 1) { if (t < o) red[t] = fmaxf(red[t], red[t + o]); __syncthreads(); }
    if (t < 32) {
        float m = red[t];
        for (int o = 16; o > 0; o >>= 1) m = fmaxf(m, __shfl_down_sync(0xffffffffu, m, o));
        if (t == 0) g_xs[(b * NSTK + s) * CIN + SPIN + c] = m;
    }
}
__global__ void k_xs_sp(const float* __restrict__ sparse) {
    int bs_ = blockIdx.x;
    int b = bs_ >> 5, s = bs_ & 31;
    int t = threadIdx.x;            // 64
    g_xs[(b * NSTK + s) * CIN + t] = sparse[(b * SPIN + t) * NSTK + s];
}

// ---------------- pairwise distances: 128x128 tile, 8x8 microtile, FFMA2, double-buffered ----------------
// Stores okey(distance) so k_topk needs no conversion.
#define DPITCH 132
__global__ void __launch_bounds__(256, 2) k_dist() {
    int bx = blockIdx.x, by = blockIdx.y;   // j-tile, i-tile
    if (by > bx) return;                    // symmetry: only upper-tri tile grid
    int b = blockIdx.z;
    int i0 = by * 128, j0 = bx * 128;
    const float* X = g_xt + (size_t)b * NPT * CIN;
    const float* x2 = g_x2 + b * NPT;
    __shared__ float As[2][16][DPITCH];
    __shared__ float Bs[2][16][DPITCH];
    int t = threadIdx.x;
    int tx = t & 15, ty = t >> 4;

    ull acc[4][8];
#pragma unroll
    for (int u = 0; u < 4; u++)
#pragma unroll
        for (int v = 0; v < 8; v++) acc[u][v] = 0ULL;

    int lr = t >> 2, kq = t & 3;
    const float* Abase = X + (size_t)(i0 + lr) * CIN + kq * 4;
    const float* Bbase = X + (size_t)(j0 + lr) * CIN + kq * 4;
    float4 pa0 = *(const float4*)(Abase);
    float4 pa1 = *(const float4*)(Abase + (size_t)64 * CIN);
    float4 pb0 = *(const float4*)(Bbase);
    float4 pb1 = *(const float4*)(Bbase + (size_t)64 * CIN);

    int kb = kq * 4;
    for (int c = 0; c < 6; c++) {
        int p = c & 1;
        As[p][kb + 0][lr] = pa0.x; As[p][kb + 1][lr] = pa0.y; As[p][kb + 2][lr] = pa0.z; As[p][kb + 3][lr] = pa0.w;
        As[p][kb + 0][lr + 64] = pa1.x; As[p][kb + 1][lr + 64] = pa1.y; As[p][kb + 2][lr + 64] = pa1.z; As[p][kb + 3][lr + 64] = pa1.w;
        Bs[p][kb + 0][lr] = pb0.x; Bs[p][kb + 1][lr] = pb0.y; Bs[p][kb + 2][lr] = pb0.z; Bs[p][kb + 3][lr] = pb0.w;
        Bs[p][kb + 0][lr + 64] = pb1.x; Bs[p][kb + 1][lr + 64] = pb1.y; Bs[p][kb + 2][lr + 64] = pb1.z; Bs[p][kb + 3][lr + 64] = pb1.w;
        __syncthreads();
        if (c < 5) {
            int ko = (c + 1) * 16;
            pa0 = *(const float4*)(Abase + ko);
            pa1 = *(const float4*)(Abase + (size_t)64 * CIN + ko);
            pb0 = *(const float4*)(Bbase + ko);
            pb1 = *(const float4*)(Bbase + (size_t)64 * CIN + ko);
        }
#pragma unroll
        for (int k = 0; k < 16; k++) {
            ull a[4];
#pragma unroll
            for (int u = 0; u < 4; u++) a[u] = *(const ull*)&As[p][k][ty * 8 + u * 2];
            float4 q0 = *(const float4*)&Bs[p][k][tx * 8];
            float4 q1 = *(const float4*)&Bs[p][k][tx * 8 + 4];
            ull bd[8];
            bd[0] = dup2(q0.x); bd[1] = dup2(q0.y); bd[2] = dup2(q0.z); bd[3] = dup2(q0.w);
            bd[4] = dup2(q1.x); bd[5] = dup2(q1.y); bd[6] = dup2(q1.z); bd[7] = dup2(q1.w);
#pragma unroll
            for (int u = 0; u < 4; u++)
#pragma unroll
                for (int v = 0; v < 8; v++) ffma2(acc[u][v], a[u], bd[v]);
        }
    }

    float x2i[8], x2j[8];
#pragma unroll
    for (int u = 0; u < 8; u++) x2i[u] = x2[i0 + ty * 8 + u];
#pragma unroll
    for (int v = 0; v < 8; v++) x2j[v] = x2[j0 + tx * 8 + v];
    unsigned d[8][8];
#pragma unroll
    for (int u = 0; u < 4; u++)
#pragma unroll
        for (int v = 0; v < 8; v++) {
            float2 p2 = unpk2(acc[u][v]);
            d[2 * u + 0][v] = okey(x2i[2 * u + 0] + x2j[v] - 2.f * p2.x);
            d[2 * u + 1][v] = okey(x2i[2 * u + 1] + x2j[v] - 2.f * p2.y);
        }
    unsigned* Dp = g_D + (size_t)b * NPT * NPT;
#pragma unroll
    for (int u = 0; u < 8; u++) {
        size_t r = (size_t)(i0 + ty * 8 + u) * NPT + j0 + tx * 8;
        uint4 w0 = make_uint4(d[u][0], d[u][1], d[u][2], d[u][3]);
        uint4 w1 = make_uint4(d[u][4], d[u][5], d[u][6], d[u][7]);
        *(uint4*)&Dp[r] = w0;
        *(uint4*)&Dp[r + 4] = w1;
    }
    if (bx != by) {
#pragma unroll
        for (int v = 0; v < 8; v++) {
            size_t r = (size_t)(j0 + tx * 8 + v) * NPT + i0 + ty * 8;
            uint4 m0 = make_uint4(d[0][v], d[1][v], d[2][v], d[3][v]);
            uint4 m1 = make_uint4(d[4][v], d[5][v], d[6][v], d[7][v]);
            *(uint4*)&Dp[r] = m0;
            *(uint4*)&Dp[r + 4] = m1;
        }
    }
}

// ---------------- top-50 per row v7: sampled prefix + exact select on candidates ----------------
__global__ void __launch_bounds__(256, 5) k_topk() {
    int row = blockIdx.x;
    const uint4* D4 = (const uint4*)(g_D + (size_t)row * NPT);
    __shared__ unsigned key[NPT];   // 32KB
    __shared__ int hist[1024];      // 4KB
    __shared__ int cand[1024];      // 4KB
    __shared__ int wsum[8];
    __shared__ unsigned sh_pref;
    __shared__ int sh_kk, sh_cless, sh_tiecnt, sh_ccnt;
    __shared__ int tielist[256];
    int t = threadIdx.x, lane = t & 31, w = t >> 5;

    // ---- sweep 1: pure streaming copy of precomputed keys ----
    for (int i = t; i < NPT / 4; i += 256)
        *(uint4*)&key[4 * i] = __ldcs(&D4[i]);
    for (int i = t; i < 1024; i += 256) hist[i] = 0;
    if (t == 0) { sh_cless = 0; sh_tiecnt = 0; sh_ccnt = 0; }
    __syncthreads();

    // ---- sampled threshold: 10-bit prefix of ~SAMPLE_K-th smallest of first SAMPLE_N keys ----
    for (int i = t; i < SAMPLE_N; i += 256) atomicAdd(&hist[key[i] >> 22], 1);
    __syncthreads();
    {
        int base = t * 4;
        int s4 = hist[base] + hist[base + 1] + hist[base + 2] + hist[base + 3];
        int incl = s4;
#pragma unroll
        for (int o = 1; o < 32; o <<= 1) { int v = __shfl_up_sync(0xffffffffu, incl, o); if (lane >= o) incl += v; }
        if (lane == 31) wsum[w] = incl;
        __syncthreads();
        if (t < 8) {
            int v = wsum[t];
#pragma unroll
            for (int o = 1; o < 8; o <<= 1) { int u2 = __shfl_up_sync(0xffu, v, o); if (t >= o) v += u2; }
            wsum[t] = v;
        }
        __syncthreads();
        int incl2 = incl + ((w > 0) ? wsum[w - 1] : 0);
        int excl = incl2 - s4;
        if (SAMPLE_K > excl && SAMPLE_K <= incl2) {
            int c = excl;
#pragma unroll
            for (int i = 0; i < 4; i++) {
                int h = hist[base + i];
                if (c + h >= SAMPLE_K) { sh_pref = (unsigned)(base + i); break; }
                c += h;
            }
        }
    }
    __syncthreads();
    unsigned cpref = sh_pref;

    // ---- compact candidates: prefix <= cpref (contains ALL keys <= any key with that prefix) ----
    for (int j = t; j < NPT; j += 256) {
        if ((key[j] >> 22) <= cpref) {
            int c = atomicAdd(&sh_ccnt, 1);
            if (c < 1024) cand[c] = j;
        }
    }
    __syncthreads();
    int ccnt = sh_ccnt;
    bool usecand = (ccnt >= KDN && ccnt <= 1024);  // sample bound held (overwhelmingly common)

    // ---- exact radix select (widths 10,8,7,7) over candidates (or full row on fallback) ----
    if (t == 0) sh_kk = KDN;
    __syncthreads();
    unsigned pref = 0u;
    const int widths[4] = {10, 8, 7, 7};
    const int shifts[4] = {22, 14, 7, 0};
    for (int pass = 0; pass < 4; ++pass) {
        int shift = shifts[pass], wd = widths[pass];
        unsigned msk = (1u << wd) - 1u;
        int nb = 1 << wd;
        for (int i = t; i < nb; i += 256) hist[i] = 0;
        __syncthreads();
        if (usecand) {
            for (int ci = t; ci < ccnt; ci += 256) {
                unsigned kx = key[cand[ci]];
                if (pass == 0 || (kx >> (shift + wd)) == pref) atomicAdd(&hist[(kx >> shift) & msk], 1);
            }
        } else {
            for (int j = t; j < NPT; j += 256) {
                unsigned kx = key[j];
                if (pass == 0 || (kx >> (shift + wd)) == pref) atomicAdd(&hist[(kx >> shift) & msk], 1);
            }
        }
        __syncthreads();
        // scan nb bins (nb up to 1024): thread t owns bins [4t,4t+4) for nb=1024 else 1 bin
        if (nb == 1024) {
            int base = t * 4;
            int s4 = hist[base] + hist[base + 1] + hist[base + 2] + hist[base + 3];
            int incl = s4;
#pragma unroll
            for (int o = 1; o < 32; o <<= 1) { int v = __shfl_up_sync(0xffffffffu, incl, o); if (lane >= o) incl += v; }
            if (lane == 31) wsum[w] = incl;
            __syncthreads();
            if (t < 8) {
                int v = wsum[t];
#pragma unroll
                for (int o = 1; o < 8; o <<= 1) { int u2 = __shfl_up_sync(0xffu, v, o); if (t >= o) v += u2; }
                wsum[t] = v;
            }
            __syncthreads();
            int incl2 = incl + ((w > 0) ? wsum[w - 1] : 0);
            int excl = incl2 - s4;
            int kk = sh_kk;
            __syncthreads();
            if (kk > excl && kk <= incl2) {
                int c = excl;
#pragma unroll
                for (int i = 0; i < 4; i++) {
                    int h = hist[base + i];
                    if (c + h >= kk) { sh_pref = (unsigned)(base + i); sh_kk = kk - c; break; }
                    c += h;
                }
            }
        } else {
            int h = (t < nb) ? hist[t] : 0;
            int inc = h;
#pragma unroll
            for (int o = 1; o < 32; o <<= 1) { int v = __shfl_up_sync(0xffffffffu, inc, o); if (lane >= o) inc += v; }
            if (lane == 31) wsum[w] = inc;
            __syncthreads();
            int wadd = 0;
            if (t < nb) { for (int ww = 0; ww < (t >> 5); ww++) wadd += wsum[ww]; }
            int inc2 = inc + wadd;
            int exc = inc2 - h;
            int kk = sh_kk;
            __syncthreads();
            if (t < nb && kk > exc && kk <= inc2) { sh_pref = (pref << wd) | (unsigned)t; sh_kk = kk - exc; }
        }
        __syncthreads();
        pref = sh_pref;
    }

    unsigned T = pref;              // exact 32-bit key of the 50th smallest
    int* outp = g_knn + (size_t)row * KDN;

    // ---- final emit ----
    if (usecand) {
        for (int ci = t; ci < ccnt; ci += 256) {
            int j = cand[ci];
            unsigned kx = key[j];
            if (kx < T) { int pos = atomicAdd(&sh_cless, 1); outp[pos] = j; }
            else if (kx == T) { int p = atomicAdd(&sh_tiecnt, 1); if (p < 256) tielist[p] = j; }
        }
    } else {
        for (int j = t; j < NPT; j += 256) {
            unsigned kx = key[j];
            if (kx < T) { int pos = atomicAdd(&sh_cless, 1); outp[pos] = j; }
            else if (kx == T) { int p = atomicAdd(&sh_tiecnt, 1); if (p < 256) tielist[p] = j; }
        }
    }
    __syncthreads();
    if (t == 0) {
        int c = sh_cless, need = KDN - c;
        int m = sh_tiecnt < 256 ? sh_tiecnt : 256;
        for (int a = 1; a < m; a++) {           // ascending index = jax stable tie-break
            int v = tielist[a], bdx = a - 1;
            while (bdx >= 0 && tielist[bdx] > v) { tielist[bdx + 1] = tielist[bdx]; bdx--; }
            tielist[bdx + 1] = v;
        }
        for (int a = 0; a < need; a++) outp[c + a] = tielist[a];
    }
}

// ---------------- A = x@W1a^T ; B = x@(W1b-W1a)^T + b1 (layer-1 factorization) ----------------
#define ABPITCH 97
__global__ void __launch_bounds__(256) k_AB(const float* __restrict__ W1, const float* __restrict__ b1) {
    extern __shared__ float sm[];
    float* Wa = sm;                           // [110][97]
    float* Wd = sm + MIDDN * ABPITCH;         // [110][97]
    float* xs = sm + 2 * MIDDN * ABPITCH;     // [16][96]
    int t = threadIdx.x;
    for (int idx = t; idx < MIDDN * CIN; idx += 256) {
        int k = idx / CIN, c = idx % CIN;
        float wa = W1[k * (2 * CIN) + c];
        float wb = W1[k * (2 * CIN) + CIN + c];
        Wa[k * ABPITCH + c] = wa;
        Wd[k * ABPITCH + c] = wb - wa;
    }
    int p0 = blockIdx.x * 16;
    for (int idx = t; idx < 16 * CIN; idx += 256)
        xs[idx] = g_xt[(size_t)(p0 + idx / CIN) * CIN + (idx % CIN)];
    __syncthreads();
    for (int idx = t; idx < 16 * MIDDN; idx += 256) {
        int pp = idx / MIDDN, k = idx % MIDDN;
        const float* xr = xs + pp * CIN;
        float a = 0.f, bb = 0.f;
#pragma unroll
        for (int c = 0; c < CIN; c++) {
            float xv = xr[c];
            a += xv * Wa[k * ABPITCH + c];
            bb += xv * Wd[k * ABPITCH + c];
        }
        size_t off = (size_t)(p0 + pp) * MIDDN + k;
        g_A[off] = a;
        g_B[off] = bb + b1[k];
    }
}

// ---------------- per-point edge MLP v4: 8 points/block, W2t staged once ----------------
#define HP 113   // pitch: (113*j + k) % 32 = (17j + k) % 32, 17 odd -> conflict-free across lanes
__global__ void __launch_bounds__(256) k_mlp(const float* __restrict__ W2, const float* __restrict__ b2) {
    extern __shared__ float dsm[];
    float* W2t = dsm;                         // [110][64]
    float* H   = dsm + MIDDN * 64;            // [50][113]
    float* Bp8 = H + KDN * HP;                // [8][112]
    int*  nbrs8 = (int*)(Bp8 + 8 * 112);      // [8][50]
    int t = threadIdx.x, lane = t & 31, w = t >> 5;
    int n0 = blockIdx.x * 8;

    for (int idx = t; idx < MIDDN * 64; idx += 256) {
        int k = idx >> 6, c = idx & 63;
        W2t[idx] = W2[c * MIDDN + k];
    }
    for (int idx = t; idx < 8 * MIDDN; idx += 256) {
        int pi = idx / MIDDN, k = idx - pi * MIDDN;
        Bp8[pi * 112 + k] = g_B[(size_t)(n0 + pi) * MIDDN + k];
    }
    for (int idx = t; idx < 8 * KDN; idx += 256) {
        int pi = idx / KDN, j = idx - pi * KDN;
        nbrs8[pi * KDN + j] = g_knn[(size_t)(n0 + pi) * KDN + j];
    }
    __syncthreads();

    for (int pi = 0; pi < 8; ++pi) {
        int n = n0 + pi, b = n >> 13, ni = n & (NPT - 1);
        const float* Bp = Bp8 + pi * 112;
        const int* nbrs = nbrs8 + pi * KDN;
        for (int idx = t; idx < KDN * MIDDN; idx += 256) {
            int j = idx / MIDDN, k = idx - j * MIDDN;
            H[j * HP + k] = lrelu(g_A[(size_t)(b * NPT + nbrs[j]) * MIDDN + k] + Bp[k]);
        }
        __syncthreads();

        bool has2 = (lane + 32) < KDN;
        const float* h0 = H + lane * HP;
        const float* h1p = H + (lane + 32) * HP;
        ull a0[4], a1[4];
#pragma unroll
        for (int i = 0; i < 4; i++) { a0[i] = 0ULL; a1[i] = 0ULL; }
        const float* Wb = W2t + w * 8;
        for (int k = 0; k < MIDDN; k++) {
            float4 wv0 = *(const float4*)&Wb[k * 64];      // broadcast within warp
            float4 wv1 = *(const float4*)&Wb[k * 64 + 4];
            ull wp[4];
            wp[0] = *(const ull*)&wv0.x; wp[1] = *(const ull*)&wv0.z;
            wp[2] = *(const ull*)&wv1.x; wp[3] = *(const ull*)&wv1.z;
            ull hd0 = dup2(h0[k]);
            ull hd1 = dup2(has2 ? h1p[k] : 0.f);
#pragma unroll
            for (int i = 0; i < 4; i++) { ffma2(a0[i], hd0, wp[i]); ffma2(a1[i], hd1, wp[i]); }
        }

        float m[8];
#pragma unroll
        for (int i = 0; i < 4; i++) {
            float bx = b2[w * 8 + 2 * i], by = b2[w * 8 + 2 * i + 1];
            float2 p0 = unpk2(a0[i]);
            float2 p1 = unpk2(a1[i]);
            float v0x = lrelu(p0.x + bx), v0y = lrelu(p0.y + by);
            float v1x = has2 ? lrelu(p1.x + bx) : -3.4e38f;
            float v1y = has2 ? lrelu(p1.y + by) : -3.4e38f;
            m[2 * i] = fmaxf(v0x, v1x);
            m[2 * i + 1] = fmaxf(v0y, v1y);
        }
#pragma unroll
        for (int o = 16; o > 0; o >>= 1)
#pragma unroll
            for (int i = 0; i < 8; i++) m[i] = fmaxf(m[i], __shfl_down_sync(0xffffffffu, m[i], o));
        if (lane == 0) {
#pragma unroll
            for (int i = 0; i < 8; i++)
                g_dnfeat[(size_t)(b * DNOUT + w * 8 + i) * NPT + ni] = m[i];
        }
        __syncthreads();   // H reused next point
    }
}

// ---------------- sparse GCN (k=2 over 32 strokes) ----------------
__global__ void __launch_bounds__(192) k_sparse(const float* __restrict__ W1, const float* __restrict__ b1,
                                                const float* __restrict__ W2, const float* __restrict__ b2,
                                                float* __restrict__ out) {
    int bi = blockIdx.x;
    int b = bi >> 5, i = bi & 31;
    __shared__ float xi[CIN];
    __shared__ float d[NSTK];
    __shared__ float h1[MIDSP];
    __shared__ int nbr2[2];
    const float* Xs = g_xs + b * NSTK * CIN;
    int t = threadIdx.x;
    if (t < CIN) xi[t] = Xs[i * CIN + t];
    __syncthreads();
    if (t < NSTK) {
        float s = 0.f;
        for (int cc = 0; cc < CIN; cc++) { float dx = Xs[t * CIN + cc] - xi[cc]; s += dx * dx; }
        d[t] = s;
    }
    __syncthreads();
    if (t == 0) {
        int i1 = 0; float v1 = d[0];
        for (int j = 1; j < NSTK; j++) if (d[j] < v1) { v1 = d[j]; i1 = j; }
        int i2 = -1; float v2 = 3.4e38f;
        for (int j = 0; j < NSTK; j++) { if (j == i1) continue; if (d[j] < v2) { v2 = d[j]; i2 = j; } }
        nbr2[0] = i1; nbr2[1] = i2;
    }
    __syncthreads();
    float acc = -3.4e38f;
    for (int jj = 0; jj < 2; jj++) {
        int nb = nbr2[jj];
        __syncthreads();
        if (t < MIDSP) {
            float s = b1[t];
            const float* w = W1 + t * (2 * CIN);
            for (int cc = 0; cc < CIN; cc++) {
                float xj = Xs[nb * CIN + cc], xc = xi[cc];
                s += (xj - xc) * w[cc] + xc * w[CIN + cc];
            }
            h1[t] = lrelu(s);
        }
        __syncthreads();
        if (t < SPOUT) {
            float s = b2[t];
            const float* w = W2 + t * MIDSP;
            for (int k = 0; k < MIDSP; k++) s += w[k] * h1[k];
            acc = fmaxf(acc, lrelu(s));
        }
    }
    if (t < SPOUT) out[(b * SPOUT + t) * NSTK + i] = acc;
}

// ---------------- downsample conv (1,3)/stride(1,2)/pad(0,1) + leaky ----------------
__global__ void __launch_bounds__(256) k_down(const float* __restrict__ dsW, const float* __restrict__ dsb,
                                              float* __restrict__ out) {
    extern __shared__ float sm[];
    float* tile = sm;                 // [64][256]
    float* Wsh = sm + DNOUT * NPNT;   // [64][64][3]
    int bs_ = blockIdx.x;
    int b = bs_ >> 5, s = bs_ & 31;
    int t = threadIdx.x;
    for (int idx = t; idx < DNOUT * NPNT; idx += 256) {
        int ic = idx >> 8, p = idx & 255;
        tile[idx] = g_dnfeat[(size_t)(b * DNOUT + ic) * NPT + s * NPNT + p];
    }
    for (int idx = t; idx < DNOUT * DNOUT * 3; idx += 256) Wsh[idx] = dsW[idx];
    __syncthreads();
    const int QO = NPNT / 2;          // 128
    for (int idx = t; idx < DNOUT * QO; idx += 256) {
        int o = idx >> 7, q = idx & 127;
        float acc = dsb[o];
        int pbase = 2 * q - 1;
        const float* wrow = Wsh + o * (DNOUT * 3);
        for (int ic = 0; ic < DNOUT; ic++) {
            const float* tr = tile + ic * NPNT;
            float w0 = wrow[ic * 3 + 0], w1 = wrow[ic * 3 + 1], w2 = wrow[ic * 3 + 2];
            float a = 0.f;
            if (pbase >= 0) a += tr[pbase] * w0;
            a += tr[pbase + 1] * w1;
            if (pbase + 2 < NPNT) a += tr[pbase + 2] * w2;
            acc += a;
        }
        out[BS * SPOUT * NSTK + (((size_t)b * DNOUT + o) * NSTK + s) * QO + q] = lrelu(acc);
    }
}

extern "C" void kernel_launch(void* const* d_in, const int* in_sizes, int n_in,
                              void* d_out, int out_size) {
    const float* sparse = (const float*)d_in[0];
    const float* dense  = (const float*)d_in[1];
    const float* spW1 = (const float*)d_in[2];
    const float* spb1 = (const float*)d_in[3];
    const float* spW2 = (const float*)d_in[4];
    const float* spb2 = (const float*)d_in[5];
    const float* dnW1 = (const float*)d_in[6];
    const float* dnb1 = (const float*)d_in[7];
    const float* dnW2 = (const float*)d_in[8];
    const float* dnb2 = (const float*)d_in[9];
    const float* dsW  = (const float*)d_in[10];
    const float* dsb  = (const float*)d_in[11];
    float* out = (float*)d_out;

    const int AB_SMEM   = (2 * MIDDN * ABPITCH + 16 * CIN) * 4;                      // ~91.5 KB
    const int MLP_SMEM  = (MIDDN * 64 + KDN * HP + 8 * 112) * 4 + 8 * KDN * 4;       // ~55.9 KB
    const int DOWN_SMEM = (DNOUT * NPNT + DNOUT * DNOUT * 3) * 4;                    // 112 KB
    cudaFuncSetAttribute(k_AB,   cudaFuncAttributeMaxDynamicSharedMemorySize, AB_SMEM);
    cudaFuncSetAttribute(k_mlp,  cudaFuncAttributeMaxDynamicSharedMemorySize, MLP_SMEM);
    cudaFuncSetAttribute(k_down, cudaFuncAttributeMaxDynamicSharedMemorySize, DOWN_SMEM);

    // Launch order: k_topk stays the 4th launch so ncu's capture window profiles it.
    k_build_xt<<<BS * NPT, CIN>>>(dense, sparse);
    k_dist<<<dim3(NPT / 128, NPT / 128, BS), 256>>>();
    k_spdn<<<BS * DNIN * NSTK, 256>>>(dense);
    k_topk<<<BS * NPT, 256>>>();
    k_xs_sp<<<BS * NSTK, SPIN>>>(sparse);
    k_AB<<<(BS * NPT) / 16, 256, AB_SMEM>>>(dnW1, dnb1);
    k_mlp<<<(BS * NPT) / 8, 256, MLP_SMEM>>>(dnW2, dnb2);
    k_sparse<<<BS * NSTK, 192>>>(spW1, spb1, spW2, spb2, out);
    k_down<<<BS * NSTK, 256, DOWN_SMEM>>>(dsW, dsb, out);
}

// round 14
// speedup vs baseline: 1.1229x; 1.1229x over previous
#include <cuda_runtime.h>
#include <cuda_bf16.h>
#include <cstddef>

#define LEAK 0.2f
#define BS 4
#define NSTK 32
#define NPNT 256
#define NPT 8192           // NSTK*NPNT
#define CIN 96
#define SPIN 64
#define DNIN 32
#define MIDDN 110
#define DNOUT 64
#define MIDSP 156
#define SPOUT 128
#define KDN 50

typedef unsigned long long ull;

// ---------------- scratch (allocation-free rule: __device__ globals) ----------------
__device__ float g_xt[(size_t)BS * NPT * CIN];       // point-major fused dense features
__device__ float g_x2[BS * NPT];
__device__ unsigned g_D[(size_t)BS * NPT * NPT];     // 1 GiB ORDERING KEYS (okey of distance)
__device__ int   g_knn[(size_t)BS * NPT * KDN];
__device__ float g_A[(size_t)BS * NPT * MIDDN];      // x @ W1a^T
__device__ float g_B[(size_t)BS * NPT * MIDDN];      // x @ (W1b-W1a)^T + b1
__device__ float g_dnfeat[(size_t)BS * DNOUT * NPT]; // channel-major GCN output
__device__ float g_xs[BS * NSTK * CIN];              // fused sparse features, point-major

__device__ __forceinline__ float lrelu(float v) { return v > 0.f ? v : LEAK * v; }

// packed f32x2 helpers (FFMA2: full-rate fp32 on sm_103a; plain FFMA is half-rate)
__device__ __forceinline__ ull dup2(float x) { ull r; asm("mov.b64 %0,{%1,%1};" : "=l"(r) : "f"(x)); return r; }
__device__ __forceinline__ void ffma2(ull& d, ull a, ull b) {
    asm("fma.rn.f32x2 %0,%1,%2,%0;" : "+l"(d) : "l"(a), "l"(b));
}
__device__ __forceinline__ float2 unpk2(ull v) { float2 f; asm("mov.b64 {%0,%1},%2;" : "=f"(f.x), "=f"(f.y) : "l"(v)); return f; }

__device__ __forceinline__ unsigned okey(float d) {
    unsigned u = __float_as_uint(d);
    return (u & 0x80000000u) ? ~u : (u | 0x80000000u);
}

// ---------------- build fused dense features + squared norms ----------------
__global__ void k_build_xt(const float* __restrict__ dense, const float* __restrict__ sparse) {
    int bn = blockIdx.x;            // b*NPT + n
    int b = bn >> 13, n = bn & (NPT - 1);
    int s = n >> 8, p = n & 255;
    int t = threadIdx.x;            // 96
    float v;
    if (t < DNIN) v = dense[(((size_t)(b * DNIN + t) * NSTK + s) << 8) + p];
    else          v = sparse[(b * SPIN + (t - DNIN)) * NSTK + s];
    g_xt[(size_t)bn * CIN + t] = v;
    __shared__ float red[CIN];
    red[t] = v * v;
    __syncthreads();
    if (t < 32) {
        float s2 = red[t] + red[t + 32] + red[t + 64];
        for (int o = 16; o > 0; o >>= 1) s2 += __shfl_down_sync(0xffffffffu, s2, o);
        if (t == 0) g_x2[bn] = s2;
    }
}

// ---------------- sparse fused features ----------------
__global__ void k_spdn(const float* __restrict__ dense) {
    int idx = blockIdx.x;           // (b, c, s)
    int b = idx >> 10, c = (idx >> 5) & 31, s = idx & 31;
    int t = threadIdx.x;            // 256
    float v = dense[(((size_t)(b * DNIN + c) * NSTK + s) << 8) + t];
    __shared__ float red[256];
    red[t] = v;
    __syncthreads();
    for (int o = 128; o >= 32; o >>= 1) { if (t < o) red[t] = fmaxf(red[t], red[t + o]); __syncthreads(); }
    if (t < 32) {
        float m = red[t];
        for (int o = 16; o > 0; o >>= 1) m = fmaxf(m, __shfl_down_sync(0xffffffffu, m, o));
        if (t == 0) g_xs[(b * NSTK + s) * CIN + SPIN + c] = m;
    }
}
__global__ void k_xs_sp(const float* __restrict__ sparse) {
    int bs_ = blockIdx.x;
    int b = bs_ >> 5, s = bs_ & 31;
    int t = threadIdx.x;            // 64
    g_xs[(b * NSTK + s) * CIN + t] = sparse[(b * SPIN + t) * NSTK + s];
}

// ---------------- pairwise distances: 128x128 tile, 8x8 microtile, FFMA2, double-buffered ----------------
// Stores okey(distance) so k_topk needs no conversion.
#define DPITCH 132
__global__ void __launch_bounds__(256, 2) k_dist() {
    int bx = blockIdx.x, by = blockIdx.y;   // j-tile, i-tile
    if (by > bx) return;                    // symmetry: only upper-tri tile grid
    int b = blockIdx.z;
    int i0 = by * 128, j0 = bx * 128;
    const float* X = g_xt + (size_t)b * NPT * CIN;
    const float* x2 = g_x2 + b * NPT;
    __shared__ float As[2][16][DPITCH];
    __shared__ float Bs[2][16][DPITCH];
    int t = threadIdx.x;
    int tx = t & 15, ty = t >> 4;

    ull acc[4][8];
#pragma unroll
    for (int u = 0; u < 4; u++)
#pragma unroll
        for (int v = 0; v < 8; v++) acc[u][v] = 0ULL;

    int lr = t >> 2, kq = t & 3;
    const float* Abase = X + (size_t)(i0 + lr) * CIN + kq * 4;
    const float* Bbase = X + (size_t)(j0 + lr) * CIN + kq * 4;
    float4 pa0 = *(const float4*)(Abase);
    float4 pa1 = *(const float4*)(Abase + (size_t)64 * CIN);
    float4 pb0 = *(const float4*)(Bbase);
    float4 pb1 = *(const float4*)(Bbase + (size_t)64 * CIN);

    int kb = kq * 4;
    for (int c = 0; c < 6; c++) {
        int p = c & 1;
        As[p][kb + 0][lr] = pa0.x; As[p][kb + 1][lr] = pa0.y; As[p][kb + 2][lr] = pa0.z; As[p][kb + 3][lr] = pa0.w;
        As[p][kb + 0][lr + 64] = pa1.x; As[p][kb + 1][lr + 64] = pa1.y; As[p][kb + 2][lr + 64] = pa1.z; As[p][kb + 3][lr + 64] = pa1.w;
        Bs[p][kb + 0][lr] = pb0.x; Bs[p][kb + 1][lr] = pb0.y; Bs[p][kb + 2][lr] = pb0.z; Bs[p][kb + 3][lr] = pb0.w;
        Bs[p][kb + 0][lr + 64] = pb1.x; Bs[p][kb + 1][lr + 64] = pb1.y; Bs[p][kb + 2][lr + 64] = pb1.z; Bs[p][kb + 3][lr + 64] = pb1.w;
        __syncthreads();
        if (c < 5) {
            int ko = (c + 1) * 16;
            pa0 = *(const float4*)(Abase + ko);
            pa1 = *(const float4*)(Abase + (size_t)64 * CIN + ko);
            pb0 = *(const float4*)(Bbase + ko);
            pb1 = *(const float4*)(Bbase + (size_t)64 * CIN + ko);
        }
#pragma unroll
        for (int k = 0; k < 16; k++) {
            ull a[4];
#pragma unroll
            for (int u = 0; u < 4; u++) a[u] = *(const ull*)&As[p][k][ty * 8 + u * 2];
            float4 q0 = *(const float4*)&Bs[p][k][tx * 8];
            float4 q1 = *(const float4*)&Bs[p][k][tx * 8 + 4];
            ull bd[8];
            bd[0] = dup2(q0.x); bd[1] = dup2(q0.y); bd[2] = dup2(q0.z); bd[3] = dup2(q0.w);
            bd[4] = dup2(q1.x); bd[5] = dup2(q1.y); bd[6] = dup2(q1.z); bd[7] = dup2(q1.w);
#pragma unroll
            for (int u = 0; u < 4; u++)
#pragma unroll
                for (int v = 0; v < 8; v++) ffma2(acc[u][v], a[u], bd[v]);
        }
    }

    float x2i[8], x2j[8];
#pragma unroll
    for (int u = 0; u < 8; u++) x2i[u] = x2[i0 + ty * 8 + u];
#pragma unroll
    for (int v = 0; v < 8; v++) x2j[v] = x2[j0 + tx * 8 + v];
    unsigned d[8][8];
#pragma unroll
    for (int u = 0; u < 4; u++)
#pragma unroll
        for (int v = 0; v < 8; v++) {
            float2 p2 = unpk2(acc[u][v]);
            d[2 * u + 0][v] = okey(x2i[2 * u + 0] + x2j[v] - 2.f * p2.x);
            d[2 * u + 1][v] = okey(x2i[2 * u + 1] + x2j[v] - 2.f * p2.y);
        }
    unsigned* Dp = g_D + (size_t)b * NPT * NPT;
#pragma unroll
    for (int u = 0; u < 8; u++) {
        size_t r = (size_t)(i0 + ty * 8 + u) * NPT + j0 + tx * 8;
        uint4 w0 = make_uint4(d[u][0], d[u][1], d[u][2], d[u][3]);
        uint4 w1 = make_uint4(d[u][4], d[u][5], d[u][6], d[u][7]);
        *(uint4*)&Dp[r] = w0;
        *(uint4*)&Dp[r + 4] = w1;
    }
    if (bx != by) {
#pragma unroll
        for (int v = 0; v < 8; v++) {
            size_t r = (size_t)(j0 + tx * 8 + v) * NPT + i0 + ty * 8;
            uint4 m0 = make_uint4(d[0][v], d[1][v], d[2][v], d[3][v]);
            uint4 m1 = make_uint4(d[4][v], d[5][v], d[6][v], d[7][v]);
            *(uint4*)&Dp[r] = m0;
            *(uint4*)&Dp[r + 4] = m1;
        }
    }
}

// ---------------- top-50 per row v6b: R12 structure, precomputed keys ----------------
__global__ void __launch_bounds__(256, 5) k_topk() {
    int row = blockIdx.x;
    const uint4* D4 = (const uint4*)(g_D + (size_t)row * NPT);
    __shared__ unsigned key[NPT];   // 32KB
    __shared__ int hist[1024];      // 4KB
    __shared__ int cand[1024];      // 4KB
    __shared__ int wsum[8];
    __shared__ unsigned sh_pref;
    __shared__ int sh_kk, sh_cless, sh_tiecnt, sh_ccnt;
    __shared__ int tielist[256];
    int t = threadIdx.x, lane = t & 31, w = t >> 5;

    for (int i = t; i < 1024; i += 256) hist[i] = 0;
    if (t == 0) { sh_kk = KDN; sh_cless = 0; sh_tiecnt = 0; sh_ccnt = 0; }
    __syncthreads();

    // ---- sweep 1: streaming copy of precomputed keys + 10-bit histogram (warp-aggregated) ----
    for (int i = t; i < NPT / 4; i += 256) {
        uint4 kv = __ldcs(&D4[i]);
        *(uint4*)&key[4 * i] = kv;
        unsigned bins[4] = {kv.x >> 22, kv.y >> 22, kv.z >> 22, kv.w >> 22};
#pragma unroll
        for (int q = 0; q < 4; q++) {
            unsigned peers = __match_any_sync(0xffffffffu, bins[q]);
            if (lane == (__ffs(peers) - 1)) atomicAdd(&hist[bins[q]], __popc(peers));
        }
    }
    __syncthreads();

    // ---- select 10-bit prefix bin (two-level scan over 1024 bins) ----
    int base = t * 4;
    int s4 = hist[base] + hist[base + 1] + hist[base + 2] + hist[base + 3];
    int incl = s4;
#pragma unroll
    for (int o = 1; o < 32; o <<= 1) { int v = __shfl_up_sync(0xffffffffu, incl, o); if (lane >= o) incl += v; }
    if (lane == 31) wsum[w] = incl;
    __syncthreads();
    if (t < 8) {
        int v = wsum[t];
#pragma unroll
        for (int o = 1; o < 8; o <<= 1) { int u2 = __shfl_up_sync(0xffu, v, o); if (t >= o) v += u2; }
        wsum[t] = v;
    }
    __syncthreads();
    int incl2 = incl + ((w > 0) ? wsum[w - 1] : 0);
    int excl = incl2 - s4;
    if (KDN > excl && KDN <= incl2) {
        int c = excl;
#pragma unroll
        for (int i = 0; i < 4; i++) {
            int h = hist[base + i];
            if (c + h >= KDN) { sh_pref = (unsigned)(base + i); sh_kk = KDN - c; break; }
            c += h;
        }
    }
    __syncthreads();
    unsigned pref = sh_pref;
    int* outp = g_knn + (size_t)row * KDN;

    // ---- sweep 2: emit provably-in (prefix < pref) + compact candidates (prefix == pref) ----
    for (int j = t; j < NPT; j += 256) {
        unsigned p = key[j] >> 22;
        if (p < pref) { int pos = atomicAdd(&sh_cless, 1); outp[pos] = j; }
        else if (p == pref) { int c = atomicAdd(&sh_ccnt, 1); if (c < 1024) cand[c] = j; }
    }
    __syncthreads();
    int ccnt = sh_ccnt;
    bool usecand = (ccnt <= 1024);

    // ---- refine passes (8,7,7 bits) over candidates only ----
    const int widths[3] = {8, 7, 7};
    const int shifts[3] = {14, 7, 0};
    for (int pass = 0; pass < 3; ++pass) {
        int shift = shifts[pass], wd = widths[pass];
        unsigned msk = (1u << wd) - 1u;
        int nb = 1 << wd;
        if (t < nb) hist[t] = 0;
        __syncthreads();
        if (usecand) {
            for (int ci = t; ci < ccnt; ci += 256) {
                unsigned kx = key[cand[ci]];
                if ((kx >> (shift + wd)) == pref) atomicAdd(&hist[(kx >> shift) & msk], 1);
            }
        } else {
            for (int j = t; j < NPT; j += 256) {
                unsigned kx = key[j];
                if ((kx >> (shift + wd)) == pref) atomicAdd(&hist[(kx >> shift) & msk], 1);
            }
        }
        __syncthreads();
        int h = (t < nb) ? hist[t] : 0;
        int inc = h;
#pragma unroll
        for (int o = 1; o < 32; o <<= 1) { int v = __shfl_up_sync(0xffffffffu, inc, o); if (lane >= o) inc += v; }
        if (lane == 31) wsum[w] = inc;
        __syncthreads();
        int wadd = 0;
        if (t < nb) { for (int ww = 0; ww < w; ww++) wadd += wsum[ww]; }
        int inc2 = inc + wadd;
        int exc = inc2 - h;
        int kk = sh_kk;
        __syncthreads();
        if (t < nb && kk > exc && kk <= inc2) { sh_pref = (pref << wd) | (unsigned)t; sh_kk = kk - exc; }
        __syncthreads();
        pref = sh_pref;
    }

    unsigned T = pref;              // exact 32-bit key of the 50th smallest
    unsigned hi = T >> 22;          // == original 10-bit prefix

    // ---- finalize among candidates only ----
    if (usecand) {
        for (int ci = t; ci < ccnt; ci += 256) {
            int j = cand[ci];
            unsigned kx = key[j];
            if (kx < T) { int pos = atomicAdd(&sh_cless, 1); outp[pos] = j; }
            else if (kx == T) { int p = atomicAdd(&sh_tiecnt, 1); if (p < 256) tielist[p] = j; }
        }
    } else {
        for (int j = t; j < NPT; j += 256) {
            unsigned kx = key[j];
            if ((kx >> 22) == hi) {
                if (kx < T) { int pos = atomicAdd(&sh_cless, 1); outp[pos] = j; }
                else if (kx == T) { int p = atomicAdd(&sh_tiecnt, 1); if (p < 256) tielist[p] = j; }
            }
        }
    }
    __syncthreads();
    if (t == 0) {
        int c = sh_cless, need = KDN - c;
        int m = sh_tiecnt < 256 ? sh_tiecnt : 256;
        for (int a = 1; a < m; a++) {           // ascending index = jax stable tie-break
            int v = tielist[a], bdx = a - 1;
            while (bdx >= 0 && tielist[bdx] > v) { tielist[bdx + 1] = tielist[bdx]; bdx--; }
            tielist[bdx + 1] = v;
        }
        for (int a = 0; a < need; a++) outp[c + a] = tielist[a];
    }
}

// ---------------- A = x@W1a^T ; B = x@(W1b-W1a)^T + b1 (layer-1 factorization) ----------------
#define ABPITCH 97
__global__ void __launch_bounds__(256) k_AB(const float* __restrict__ W1, const float* __restrict__ b1) {
    extern __shared__ float sm[];
    float* Wa = sm;                           // [110][97]
    float* Wd = sm + MIDDN * ABPITCH;         // [110][97]
    float* xs = sm + 2 * MIDDN * ABPITCH;     // [16][96]
    int t = threadIdx.x;
    for (int idx = t; idx < MIDDN * CIN; idx += 256) {
        int k = idx / CIN, c = idx % CIN;
        float wa = W1[k * (2 * CIN) + c];
        float wb = W1[k * (2 * CIN) + CIN + c];
        Wa[k * ABPITCH + c] = wa;
        Wd[k * ABPITCH + c] = wb - wa;
    }
    int p0 = blockIdx.x * 16;
    for (int idx = t; idx < 16 * CIN; idx += 256)
        xs[idx] = g_xt[(size_t)(p0 + idx / CIN) * CIN + (idx % CIN)];
    __syncthreads();
    for (int idx = t; idx < 16 * MIDDN; idx += 256) {
        int pp = idx / MIDDN, k = idx % MIDDN;
        const float* xr = xs + pp * CIN;
        float a = 0.f, bb = 0.f;
#pragma unroll
        for (int c = 0; c < CIN; c++) {
            float xv = xr[c];
            a += xv * Wa[k * ABPITCH + c];
            bb += xv * Wd[k * ABPITCH + c];
        }
        size_t off = (size_t)(p0 + pp) * MIDDN + k;
        g_A[off] = a;
        g_B[off] = bb + b1[k];
    }
}

// ---------------- per-point edge MLP v4: 8 points/block, W2t staged once ----------------
#define HP 113   // pitch: (113*j + k) % 32 = (17j + k) % 32, 17 odd -> conflict-free across lanes
__global__ void __launch_bounds__(256) k_mlp(const float* __restrict__ W2, const float* __restrict__ b2) {
    extern __shared__ float dsm[];
    float* W2t = dsm;                         // [110][64]
    float* H   = dsm + MIDDN * 64;            // [50][113]
    float* Bp8 = H + KDN * HP;                // [8][112]
    int*  nbrs8 = (int*)(Bp8 + 8 * 112);      // [8][50]
    int t = threadIdx.x, lane = t & 31, w = t >> 5;
    int n0 = blockIdx.x * 8;

    for (int idx = t; idx < MIDDN * 64; idx += 256) {
        int k = idx >> 6, c = idx & 63;
        W2t[idx] = W2[c * MIDDN + k];
    }
    for (int idx = t; idx < 8 * MIDDN; idx += 256) {
        int pi = idx / MIDDN, k = idx - pi * MIDDN;
        Bp8[pi * 112 + k] = g_B[(size_t)(n0 + pi) * MIDDN + k];
    }
    for (int idx = t; idx < 8 * KDN; idx += 256) {
        int pi = idx / KDN, j = idx - pi * KDN;
        nbrs8[pi * KDN + j] = g_knn[(size_t)(n0 + pi) * KDN + j];
    }
    __syncthreads();

    for (int pi = 0; pi < 8; ++pi) {
        int n = n0 + pi, b = n >> 13, ni = n & (NPT - 1);
        const float* Bp = Bp8 + pi * 112;
        const int* nbrs = nbrs8 + pi * KDN;
        for (int idx = t; idx < KDN * MIDDN; idx += 256) {
            int j = idx / MIDDN, k = idx - j * MIDDN;
            H[j * HP + k] = lrelu(g_A[(size_t)(b * NPT + nbrs[j]) * MIDDN + k] + Bp[k]);
        }
        __syncthreads();

        bool has2 = (lane + 32) < KDN;
        const float* h0 = H + lane * HP;
        const float* h1p = H + (lane + 32) * HP;
        ull a0[4], a1[4];
#pragma unroll
        for (int i = 0; i < 4; i++) { a0[i] = 0ULL; a1[i] = 0ULL; }
        const float* Wb = W2t + w * 8;
        for (int k = 0; k < MIDDN; k++) {
            float4 wv0 = *(const float4*)&Wb[k * 64];      // broadcast within warp
            float4 wv1 = *(const float4*)&Wb[k * 64 + 4];
            ull wp[4];
            wp[0] = *(const ull*)&wv0.x; wp[1] = *(const ull*)&wv0.z;
            wp[2] = *(const ull*)&wv1.x; wp[3] = *(const ull*)&wv1.z;
            ull hd0 = dup2(h0[k]);
            ull hd1 = dup2(has2 ? h1p[k] : 0.f);
#pragma unroll
            for (int i = 0; i < 4; i++) { ffma2(a0[i], hd0, wp[i]); ffma2(a1[i], hd1, wp[i]); }
        }

        float m[8];
#pragma unroll
        for (int i = 0; i < 4; i++) {
            float bx = b2[w * 8 + 2 * i], by = b2[w * 8 + 2 * i + 1];
            float2 p0 = unpk2(a0[i]);
            float2 p1 = unpk2(a1[i]);
            float v0x = lrelu(p0.x + bx), v0y = lrelu(p0.y + by);
            float v1x = has2 ? lrelu(p1.x + bx) : -3.4e38f;
            float v1y = has2 ? lrelu(p1.y + by) : -3.4e38f;
            m[2 * i] = fmaxf(v0x, v1x);
            m[2 * i + 1] = fmaxf(v0y, v1y);
        }
#pragma unroll
        for (int o = 16; o > 0; o >>= 1)
#pragma unroll
            for (int i = 0; i < 8; i++) m[i] = fmaxf(m[i], __shfl_down_sync(0xffffffffu, m[i], o));
        if (lane == 0) {
#pragma unroll
            for (int i = 0; i < 8; i++)
                g_dnfeat[(size_t)(b * DNOUT + w * 8 + i) * NPT + ni] = m[i];
        }
        __syncthreads();   // H reused next point
    }
}

// ---------------- sparse GCN (k=2 over 32 strokes) ----------------
__global__ void __launch_bounds__(192) k_sparse(const float* __restrict__ W1, const float* __restrict__ b1,
                                                const float* __restrict__ W2, const float* __restrict__ b2,
                                                float* __restrict__ out) {
    int bi = blockIdx.x;
    int b = bi >> 5, i = bi & 31;
    __shared__ float xi[CIN];
    __shared__ float d[NSTK];
    __shared__ float h1[MIDSP];
    __shared__ int nbr2[2];
    const float* Xs = g_xs + b * NSTK * CIN;
    int t = threadIdx.x;
    if (t < CIN) xi[t] = Xs[i * CIN + t];
    __syncthreads();
    if (t < NSTK) {
        float s = 0.f;
        for (int cc = 0; cc < CIN; cc++) { float dx = Xs[t * CIN + cc] - xi[cc]; s += dx * dx; }
        d[t] = s;
    }
    __syncthreads();
    if (t == 0) {
        int i1 = 0; float v1 = d[0];
        for (int j = 1; j < NSTK; j++) if (d[j] < v1) { v1 = d[j]; i1 = j; }
        int i2 = -1; float v2 = 3.4e38f;
        for (int j = 0; j < NSTK; j++) { if (j == i1) continue; if (d[j] < v2) { v2 = d[j]; i2 = j; } }
        nbr2[0] = i1; nbr2[1] = i2;
    }
    __syncthreads();
    float acc = -3.4e38f;
    for (int jj = 0; jj < 2; jj++) {
        int nb = nbr2[jj];
        __syncthreads();
        if (t < MIDSP) {
            float s = b1[t];
            const float* w = W1 + t * (2 * CIN);
            for (int cc = 0; cc < CIN; cc++) {
                float xj = Xs[nb * CIN + cc], xc = xi[cc];
                s += (xj - xc) * w[cc] + xc * w[CIN + cc];
            }
            h1[t] = lrelu(s);
        }
        __syncthreads();
        if (t < SPOUT) {
            float s = b2[t];
            const float* w = W2 + t * MIDSP;
            for (int k = 0; k < MIDSP; k++) s += w[k] * h1[k];
            acc = fmaxf(acc, lrelu(s));
        }
    }
    if (t < SPOUT) out[(b * SPOUT + t) * NSTK + i] = acc;
}

// ---------------- downsample conv (1,3)/stride(1,2)/pad(0,1) + leaky ----------------
__global__ void __launch_bounds__(256) k_down(const float* __restrict__ dsW, const float* __restrict__ dsb,
                                              float* __restrict__ out) {
    extern __shared__ float sm[];
    float* tile = sm;                 // [64][256]
    float* Wsh = sm + DNOUT * NPNT;   // [64][64][3]
    int bs_ = blockIdx.x;
    int b = bs_ >> 5, s = bs_ & 31;
    int t = threadIdx.x;
    for (int idx = t; idx < DNOUT * NPNT; idx += 256) {
        int ic = idx >> 8, p = idx & 255;
        tile[idx] = g_dnfeat[(size_t)(b * DNOUT + ic) * NPT + s * NPNT + p];
    }
    for (int idx = t; idx < DNOUT * DNOUT * 3; idx += 256) Wsh[idx] = dsW[idx];
    __syncthreads();
    const int QO = NPNT / 2;          // 128
    for (int idx = t; idx < DNOUT * QO; idx += 256) {
        int o = idx >> 7, q = idx & 127;
        float acc = dsb[o];
        int pbase = 2 * q - 1;
        const float* wrow = Wsh + o * (DNOUT * 3);
        for (int ic = 0; ic < DNOUT; ic++) {
            const float* tr = tile + ic * NPNT;
            float w0 = wrow[ic * 3 + 0], w1 = wrow[ic * 3 + 1], w2 = wrow[ic * 3 + 2];
            float a = 0.f;
            if (pbase >= 0) a += tr[pbase] * w0;
            a += tr[pbase + 1] * w1;
            if (pbase + 2 < NPNT) a += tr[pbase + 2] * w2;
            acc += a;
        }
        out[BS * SPOUT * NSTK + (((size_t)b * DNOUT + o) * NSTK + s) * QO + q] = lrelu(acc);
    }
}

extern "C" void kernel_launch(void* const* d_in, const int* in_sizes, int n_in,
                              void* d_out, int out_size) {
    const float* sparse = (const float*)d_in[0];
    const float* dense  = (const float*)d_in[1];
    const float* spW1 = (const float*)d_in[2];
    const float* spb1 = (const float*)d_in[3];
    const float* spW2 = (const float*)d_in[4];
    const float* spb2 = (const float*)d_in[5];
    const float* dnW1 = (const float*)d_in[6];
    const float* dnb1 = (const float*)d_in[7];
    const float* dnW2 = (const float*)d_in[8];
    const float* dnb2 = (const float*)d_in[9];
    const float* dsW  = (const float*)d_in[10];
    const float* dsb  = (const float*)d_in[11];
    float* out = (float*)d_out;

    const int AB_SMEM   = (2 * MIDDN * ABPITCH + 16 * CIN) * 4;                      // ~91.5 KB
    const int MLP_SMEM  = (MIDDN * 64 + KDN * HP + 8 * 112) * 4 + 8 * KDN * 4;       // ~55.9 KB
    const int DOWN_SMEM = (DNOUT * NPNT + DNOUT * DNOUT * 3) * 4;                    // 112 KB
    cudaFuncSetAttribute(k_AB,   cudaFuncAttributeMaxDynamicSharedMemorySize, AB_SMEM);
    cudaFuncSetAttribute(k_mlp,  cudaFuncAttributeMaxDynamicSharedMemorySize, MLP_SMEM);
    cudaFuncSetAttribute(k_down, cudaFuncAttributeMaxDynamicSharedMemorySize, DOWN_SMEM);

    // Launch order: k_topk stays the 4th launch so ncu's capture window profiles it.
    k_build_xt<<<BS * NPT, CIN>>>(dense, sparse);
    k_dist<<<dim3(NPT / 128, NPT / 128, BS), 256>>>();
    k_spdn<<<BS * DNIN * NSTK, 256>>>(dense);
    k_topk<<<BS * NPT, 256>>>();
    k_xs_sp<<<BS * NSTK, SPIN>>>(sparse);
    k_AB<<<(BS * NPT) / 16, 256, AB_SMEM>>>(dnW1, dnb1);
    k_mlp<<<(BS * NPT) / 8, 256, MLP_SMEM>>>(dnW2, dnb2);
    k_sparse<<<BS * NSTK, 192>>>(spW1, spb1, spW2, spb2, out);
    k_down<<<BS * NSTK, 256, DOWN_SMEM>>>(dsW, dsb, out);
}

// round 16
// speedup vs baseline: 1.1481x; 1.0224x over previous
#include <cuda_runtime.h>
#include <cuda_bf16.h>
#include <cstddef>

#define LEAK 0.2f
#define BS 4
#define NSTK 32
#define NPNT 256
#define NPT 8192           // NSTK*NPNT
#define CIN 96
#define SPIN 64
#define DNIN 32
#define MIDDN 110
#define DNOUT 64
#define MIDSP 156
#define SPOUT 128
#define KDN 50

typedef unsigned long long ull;

// ---------------- scratch (allocation-free rule: __device__ globals) ----------------
__device__ float g_xt[(size_t)BS * NPT * CIN];       // point-major fused dense features
__device__ float g_x2[BS * NPT];
__device__ unsigned g_D[(size_t)BS * NPT * NPT];     // 1 GiB ORDERING KEYS (okey of distance)
__device__ int   g_knn[(size_t)BS * NPT * KDN];
__device__ float g_A[(size_t)BS * NPT * MIDDN];      // x @ W1a^T
__device__ float g_B[(size_t)BS * NPT * MIDDN];      // x @ (W1b-W1a)^T + b1
__device__ float g_dnfeat[(size_t)BS * DNOUT * NPT]; // channel-major GCN output
__device__ float g_xs[BS * NSTK * CIN];              // fused sparse features, point-major

__device__ __forceinline__ float lrelu(float v) { return v > 0.f ? v : LEAK * v; }

// packed f32x2 helpers (FFMA2 on sm_103a: saves issue slots vs 2x FFMA)
__device__ __forceinline__ ull dup2(float x) { ull r; asm("mov.b64 %0,{%1,%1};" : "=l"(r) : "f"(x)); return r; }
__device__ __forceinline__ void ffma2(ull& d, ull a, ull b) {
    asm("fma.rn.f32x2 %0,%1,%2,%0;" : "+l"(d) : "l"(a), "l"(b));
}
__device__ __forceinline__ float2 unpk2(ull v) { float2 f; asm("mov.b64 {%0,%1},%2;" : "=f"(f.x), "=f"(f.y) : "l"(v)); return f; }

__device__ __forceinline__ unsigned okey(float d) {
    unsigned u = __float_as_uint(d);
    return (u & 0x80000000u) ? ~u : (u | 0x80000000u);
}

// ---------------- build fused dense features + squared norms ----------------
__global__ void k_build_xt(const float* __restrict__ dense, const float* __restrict__ sparse) {
    int bn = blockIdx.x;            // b*NPT + n
    int b = bn >> 13, n = bn & (NPT - 1);
    int s = n >> 8, p = n & 255;
    int t = threadIdx.x;            // 96
    float v;
    if (t < DNIN) v = dense[(((size_t)(b * DNIN + t) * NSTK + s) << 8) + p];
    else          v = sparse[(b * SPIN + (t - DNIN)) * NSTK + s];
    g_xt[(size_t)bn * CIN + t] = v;
    __shared__ float red[CIN];
    red[t] = v * v;
    __syncthreads();
    if (t < 32) {
        float s2 = red[t] + red[t + 32] + red[t + 64];
        for (int o = 16; o > 0; o >>= 1) s2 += __shfl_down_sync(0xffffffffu, s2, o);
        if (t == 0) g_x2[bn] = s2;
    }
}

// ---------------- sparse fused features ----------------
__global__ void k_spdn(const float* __restrict__ dense) {
    int idx = blockIdx.x;           // (b, c, s)
    int b = idx >> 10, c = (idx >> 5) & 31, s = idx & 31;
    int t = threadIdx.x;            // 256
    float v = dense[(((size_t)(b * DNIN + c) * NSTK + s) << 8) + t];
    __shared__ float red[256];
    red[t] = v;
    __syncthreads();
    for (int o = 128; o >= 32; o >>= 1) { if (t < o) red[t] = fmaxf(red[t], red[t + o]); __syncthreads(); }
    if (t < 32) {
        float m = red[t];
        for (int o = 16; o > 0; o >>= 1) m = fmaxf(m, __shfl_down_sync(0xffffffffu, m, o));
        if (t == 0) g_xs[(b * NSTK + s) * CIN + SPIN + c] = m;
    }
}
__global__ void k_xs_sp(const float* __restrict__ sparse) {
    int bs_ = blockIdx.x;
    int b = bs_ >> 5, s = bs_ & 31;
    int t = threadIdx.x;            // 64
    g_xs[(b * NSTK + s) * CIN + t] = sparse[(b * SPIN + t) * NSTK + s];
}

// ---------------- pairwise distances: 128x128 tile, 8x8 microtile, FFMA2, double-buffered ----------------
// Stores okey(distance) so k_topk needs no conversion.
#define DPITCH 132
__global__ void __launch_bounds__(256, 2) k_dist() {
    int bx = blockIdx.x, by = blockIdx.y;   // j-tile, i-tile
    if (by > bx) return;                    // symmetry: only upper-tri tile grid
    int b = blockIdx.z;
    int i0 = by * 128, j0 = bx * 128;
    const float* X = g_xt + (size_t)b * NPT * CIN;
    const float* x2 = g_x2 + b * NPT;
    __shared__ float As[2][16][DPITCH];
    __shared__ float Bs[2][16][DPITCH];
    int t = threadIdx.x;
    int tx = t & 15, ty = t >> 4;

    ull acc[4][8];
#pragma unroll
    for (int u = 0; u < 4; u++)
#pragma unroll
        for (int v = 0; v < 8; v++) acc[u][v] = 0ULL;

    int lr = t >> 2, kq = t & 3;
    const float* Abase = X + (size_t)(i0 + lr) * CIN + kq * 4;
    const float* Bbase = X + (size_t)(j0 + lr) * CIN + kq * 4;
    float4 pa0 = *(const float4*)(Abase);
    float4 pa1 = *(const float4*)(Abase + (size_t)64 * CIN);
    float4 pb0 = *(const float4*)(Bbase);
    float4 pb1 = *(const float4*)(Bbase + (size_t)64 * CIN);

    int kb = kq * 4;
    for (int c = 0; c < 6; c++) {
        int p = c & 1;
        As[p][kb + 0][lr] = pa0.x; As[p][kb + 1][lr] = pa0.y; As[p][kb + 2][lr] = pa0.z; As[p][kb + 3][lr] = pa0.w;
        As[p][kb + 0][lr + 64] = pa1.x; As[p][kb + 1][lr + 64] = pa1.y; As[p][kb + 2][lr + 64] = pa1.z; As[p][kb + 3][lr + 64] = pa1.w;
        Bs[p][kb + 0][lr] = pb0.x; Bs[p][kb + 1][lr] = pb0.y; Bs[p][kb + 2][lr] = pb0.z; Bs[p][kb + 3][lr] = pb0.w;
        Bs[p][kb + 0][lr + 64] = pb1.x; Bs[p][kb + 1][lr + 64] = pb1.y; Bs[p][kb + 2][lr + 64] = pb1.z; Bs[p][kb + 3][lr + 64] = pb1.w;
        __syncthreads();
        if (c < 5) {
            int ko = (c + 1) * 16;
            pa0 = *(const float4*)(Abase + ko);
            pa1 = *(const float4*)(Abase + (size_t)64 * CIN + ko);
            pb0 = *(const float4*)(Bbase + ko);
            pb1 = *(const float4*)(Bbase + (size_t)64 * CIN + ko);
        }
#pragma unroll
        for (int k = 0; k < 16; k++) {
            ull a[4];
#pragma unroll
            for (int u = 0; u < 4; u++) a[u] = *(const ull*)&As[p][k][ty * 8 + u * 2];
            float4 q0 = *(const float4*)&Bs[p][k][tx * 8];
            float4 q1 = *(const float4*)&Bs[p][k][tx * 8 + 4];
            ull bd[8];
            bd[0] = dup2(q0.x); bd[1] = dup2(q0.y); bd[2] = dup2(q0.z); bd[3] = dup2(q0.w);
            bd[4] = dup2(q1.x); bd[5] = dup2(q1.y); bd[6] = dup2(q1.z); bd[7] = dup2(q1.w);
#pragma unroll
            for (int u = 0; u < 4; u++)
#pragma unroll
                for (int v = 0; v < 8; v++) ffma2(acc[u][v], a[u], bd[v]);
        }
    }

    float x2i[8], x2j[8];
#pragma unroll
    for (int u = 0; u < 8; u++) x2i[u] = x2[i0 + ty * 8 + u];
#pragma unroll
    for (int v = 0; v < 8; v++) x2j[v] = x2[j0 + tx * 8 + v];
    unsigned d[8][8];
#pragma unroll
    for (int u = 0; u < 4; u++)
#pragma unroll
        for (int v = 0; v < 8; v++) {
            float2 p2 = unpk2(acc[u][v]);
            d[2 * u + 0][v] = okey(x2i[2 * u + 0] + x2j[v] - 2.f * p2.x);
            d[2 * u + 1][v] = okey(x2i[2 * u + 1] + x2j[v] - 2.f * p2.y);
        }
    unsigned* Dp = g_D + (size_t)b * NPT * NPT;
#pragma unroll
    for (int u = 0; u < 8; u++) {
        size_t r = (size_t)(i0 + ty * 8 + u) * NPT + j0 + tx * 8;
        uint4 w0 = make_uint4(d[u][0], d[u][1], d[u][2], d[u][3]);
        uint4 w1 = make_uint4(d[u][4], d[u][5], d[u][6], d[u][7]);
        *(uint4*)&Dp[r] = w0;
        *(uint4*)&Dp[r + 4] = w1;
    }
    if (bx != by) {
#pragma unroll
        for (int v = 0; v < 8; v++) {
            size_t r = (size_t)(j0 + tx * 8 + v) * NPT + i0 + ty * 8;
            uint4 m0 = make_uint4(d[0][v], d[1][v], d[2][v], d[3][v]);
            uint4 m1 = make_uint4(d[4][v], d[5][v], d[6][v], d[7][v]);
            *(uint4*)&Dp[r] = m0;
            *(uint4*)&Dp[r + 4] = m1;
        }
    }
}

// ---------------- top-50 per row v9: stratified sample + count-verified threshold + exact fallback ----------------
// Sample key[32*t] (uniform over strokes). Order stats rank {8,24} give escalating thresholds.
// Streaming pass counts AND compacts {key <= T}. Accept ONLY if 50 <= c <= 1024 (count is exact).
// Otherwise run a fully exact radix select over the whole row from gmem (L2-resident).
__global__ void __launch_bounds__(256, 8) k_topk() {
    int row = blockIdx.x;
    const unsigned* K = g_D + (size_t)row * NPT;
    const uint4* K4 = (const uint4*)K;
    __shared__ unsigned samp[256];
    __shared__ unsigned sh_T[2];
    __shared__ int hist[1024];
    __shared__ unsigned ckey[1024];
    __shared__ int cidx[1024];
    __shared__ int wsum[8];
    __shared__ unsigned sh_pref;
    __shared__ int sh_kk, sh_cless, sh_tiecnt, sh_cc;
    __shared__ int tielist[256];
    int t = threadIdx.x, lane = t & 31, w = t >> 5;

    samp[t] = K[t << 5];            // stratified: every 32nd key, covers all strokes
    if (t < 2) sh_T[t] = 0u;
    __syncthreads();

    // sample order statistics via rank counting (256 elements, 1 per thread)
    {
        unsigned v = samp[t];
        int cnt = 0;
#pragma unroll 8
        for (int j = 0; j < 256; j++) cnt += (samp[j] < v) ? 1 : 0;
        if (cnt < 8)  atomicMax(&sh_T[0], v);   // ~rank-8 stat  -> E[c] ~ 255
        if (cnt < 24) atomicMax(&sh_T[1], v);   // ~rank-24 stat -> E[c] ~ 765
    }
    __syncthreads();

    // streaming count + compact; accept only if count is verifiably in range
    int c = 0;
    bool ok = false;
    for (int level = 0; level < 2; level++) {
        if (t == 0) sh_cc = 0;
        __syncthreads();
        unsigned T = sh_T[level];
        for (int i = t; i < NPT / 4; i += 256) {
            uint4 kv = K4[i];               // default caching: retries hit L2
            bool m0 = kv.x <= T, m1 = kv.y <= T, m2 = kv.z <= T, m3 = kv.w <= T;
            if (m0 | m1 | m2 | m3) {
                int j = 4 * i;
                if (m0) { int p = atomicAdd(&sh_cc, 1); if (p < 1024) { ckey[p] = kv.x; cidx[p] = j; } }
                if (m1) { int p = atomicAdd(&sh_cc, 1); if (p < 1024) { ckey[p] = kv.y; cidx[p] = j + 1; } }
                if (m2) { int p = atomicAdd(&sh_cc, 1); if (p < 1024) { ckey[p] = kv.z; cidx[p] = j + 2; } }
                if (m3) { int p = atomicAdd(&sh_cc, 1); if (p < 1024) { ckey[p] = kv.w; cidx[p] = j + 3; } }
            }
        }
        __syncthreads();
        c = sh_cc;                          // exact count of {key <= T}
        __syncthreads();                    // protect sh_cc reset next iteration
        if (c >= KDN && c <= 1024) { ok = true; break; }
        if (c > 1024) break;                // larger thresholds only worse -> exact fallback
    }
    int m = c < 1024 ? c : 1024;

    // exact radix select (widths 10,8,7,7) for the KDN-th smallest
    // over candidates (ok) or the full row from gmem (fallback; always exact)
    if (t == 0) { sh_kk = KDN; sh_cless = 0; sh_tiecnt = 0; }
    __syncthreads();
    unsigned pref = 0u;
    const int widths[4] = {10, 8, 7, 7};
    const int shifts[4] = {22, 14, 7, 0};
    for (int pass = 0; pass < 4; ++pass) {
        int shift = shifts[pass], wd = widths[pass];
        unsigned msk = (1u << wd) - 1u;
        int nb = 1 << wd;
        for (int i = t; i < nb; i += 256) hist[i] = 0;
        __syncthreads();
        if (ok) {
            for (int ci = t; ci < m; ci += 256) {
                unsigned kx = ckey[ci];
                if (pass == 0 || (kx >> (shift + wd)) == pref) atomicAdd(&hist[(kx >> shift) & msk], 1);
            }
        } else {
            for (int j = t; j < NPT; j += 256) {
                unsigned kx = K[j];
                if (pass == 0 || (kx >> (shift + wd)) == pref) atomicAdd(&hist[(kx >> shift) & msk], 1);
            }
        }
        __syncthreads();
        if (nb == 1024) {
            int base = t * 4;
            int s4 = hist[base] + hist[base + 1] + hist[base + 2] + hist[base + 3];
            int incl = s4;
#pragma unroll
            for (int o = 1; o < 32; o <<= 1) { int v = __shfl_up_sync(0xffffffffu, incl, o); if (lane >= o) incl += v; }
            if (lane == 31) wsum[w] = incl;
            __syncthreads();
            if (t < 8) {
                int v = wsum[t];
#pragma unroll
                for (int o = 1; o < 8; o <<= 1) { int u2 = __shfl_up_sync(0xffu, v, o); if (t >= o) v += u2; }
                wsum[t] = v;
            }
            __syncthreads();
            int incl2 = incl + ((w > 0) ? wsum[w - 1] : 0);
            int excl = incl2 - s4;
            int kk = sh_kk;
            __syncthreads();
            if (kk > excl && kk <= incl2) {
                int cc = excl;
#pragma unroll
                for (int i = 0; i < 4; i++) {
                    int h = hist[base + i];
                    if (cc + h >= kk) { sh_pref = (unsigned)(base + i); sh_kk = kk - cc; break; }
                    cc += h;
                }
            }
        } else {
            int h = (t < nb) ? hist[t] : 0;
            int inc = h;
#pragma unroll
            for (int o = 1; o < 32; o <<= 1) { int v = __shfl_up_sync(0xffffffffu, inc, o); if (lane >= o) inc += v; }
            if (lane == 31) wsum[w] = inc;
            __syncthreads();
            int wadd = 0;
            if (t < nb) { for (int ww = 0; ww < (t >> 5); ww++) wadd += wsum[ww]; }
            int inc2 = inc + wadd;
            int exc = inc2 - h;
            int kk = sh_kk;
            __syncthreads();
            if (t < nb && kk > exc && kk <= inc2) { sh_pref = (pref << wd) | (unsigned)t; sh_kk = kk - exc; }
        }
        __syncthreads();
        pref = sh_pref;
    }

    unsigned T = pref;              // exact 32-bit key of the KDN-th smallest
    int* outp = g_knn + (size_t)row * KDN;
    if (ok) {
        for (int ci = t; ci < m; ci += 256) {
            unsigned kx = ckey[ci];
            if (kx < T) { int pos = atomicAdd(&sh_cless, 1); outp[pos] = cidx[ci]; }
            else if (kx == T) { int p = atomicAdd(&sh_tiecnt, 1); if (p < 256) tielist[p] = cidx[ci]; }
        }
    } else {
        for (int j = t; j < NPT; j += 256) {
            unsigned kx = K[j];
            if (kx < T) { int pos = atomicAdd(&sh_cless, 1); outp[pos] = j; }
            else if (kx == T) { int p = atomicAdd(&sh_tiecnt, 1); if (p < 256) tielist[p] = j; }
        }
    }
    __syncthreads();
    if (t == 0) {
        int cl = sh_cless, need = KDN - cl;
        int mm = sh_tiecnt < 256 ? sh_tiecnt : 256;
        for (int a = 1; a < mm; a++) {          // ascending index = jax stable tie-break
            int v = tielist[a], bdx = a - 1;
            while (bdx >= 0 && tielist[bdx] > v) { tielist[bdx + 1] = tielist[bdx]; bdx--; }
            tielist[bdx + 1] = v;
        }
        for (int a = 0; a < need; a++) outp[cl + a] = tielist[a];
    }
}

// ---------------- A = x@W1a^T ; B = x@(W1b-W1a)^T + b1 (layer-1 factorization) ----------------
#define ABPITCH 97
__global__ void __launch_bounds__(256) k_AB(const float* __restrict__ W1, const float* __restrict__ b1) {
    extern __shared__ float sm[];
    float* Wa = sm;                           // [110][97]
    float* Wd = sm + MIDDN * ABPITCH;         // [110][97]
    float* xs = sm + 2 * MIDDN * ABPITCH;     // [16][96]
    int t = threadIdx.x;
    for (int idx = t; idx < MIDDN * CIN; idx += 256) {
        int k = idx / CIN, c = idx % CIN;
        float wa = W1[k * (2 * CIN) + c];
        float wb = W1[k * (2 * CIN) + CIN + c];
        Wa[k * ABPITCH + c] = wa;
        Wd[k * ABPITCH + c] = wb - wa;
    }
    int p0 = blockIdx.x * 16;
    for (int idx = t; idx < 16 * CIN; idx += 256)
        xs[idx] = g_xt[(size_t)(p0 + idx / CIN) * CIN + (idx % CIN)];
    __syncthreads();
    for (int idx = t; idx < 16 * MIDDN; idx += 256) {
        int pp = idx / MIDDN, k = idx % MIDDN;
        const float* xr = xs + pp * CIN;
        float a = 0.f, bb = 0.f;
#pragma unroll
        for (int c = 0; c < CIN; c++) {
            float xv = xr[c];
            a += xv * Wa[k * ABPITCH + c];
            bb += xv * Wd[k * ABPITCH + c];
        }
        size_t off = (size_t)(p0 + pp) * MIDDN + k;
        g_A[off] = a;
        g_B[off] = bb + b1[k];
    }
}

// ---------------- per-point edge MLP v4: 8 points/block, W2t staged once ----------------
#define HP 113   // pitch: (113*j + k) % 32 = (17j + k) % 32, 17 odd -> conflict-free across lanes
__global__ void __launch_bounds__(256) k_mlp(const float* __restrict__ W2, const float* __restrict__ b2) {
    extern __shared__ float dsm[];
    float* W2t = dsm;                         // [110][64]
    float* H   = dsm + MIDDN * 64;            // [50][113]
    float* Bp8 = H + KDN * HP;                // [8][112]
    int*  nbrs8 = (int*)(Bp8 + 8 * 112);      // [8][50]
    int t = threadIdx.x, lane = t & 31, w = t >> 5;
    int n0 = blockIdx.x * 8;

    for (int idx = t; idx < MIDDN * 64; idx += 256) {
        int k = idx >> 6, c = idx & 63;
        W2t[idx] = W2[c * MIDDN + k];
    }
    for (int idx = t; idx < 8 * MIDDN; idx += 256) {
        int pi = idx / MIDDN, k = idx - pi * MIDDN;
        Bp8[pi * 112 + k] = g_B[(size_t)(n0 + pi) * MIDDN + k];
    }
    for (int idx = t; idx < 8 * KDN; idx += 256) {
        int pi = idx / KDN, j = idx - pi * KDN;
        nbrs8[pi * KDN + j] = g_knn[(size_t)(n0 + pi) * KDN + j];
    }
    __syncthreads();

    for (int pi = 0; pi < 8; ++pi) {
        int n = n0 + pi, b = n >> 13, ni = n & (NPT - 1);
        const float* Bp = Bp8 + pi * 112;
        const int* nbrs = nbrs8 + pi * KDN;
        for (int idx = t; idx < KDN * MIDDN; idx += 256) {
            int j = idx / MIDDN, k = idx - j * MIDDN;
            H[j * HP + k] = lrelu(g_A[(size_t)(b * NPT + nbrs[j]) * MIDDN + k] + Bp[k]);
        }
        __syncthreads();

        bool has2 = (lane + 32) < KDN;
        const float* h0 = H + lane * HP;
        const float* h1p = H + (lane + 32) * HP;
        ull a0[4], a1[4];
#pragma unroll
        for (int i = 0; i < 4; i++) { a0[i] = 0ULL; a1[i] = 0ULL; }
        const float* Wb = W2t + w * 8;
        for (int k = 0; k < MIDDN; k++) {
            float4 wv0 = *(const float4*)&Wb[k * 64];      // broadcast within warp
            float4 wv1 = *(const float4*)&Wb[k * 64 + 4];
            ull wp[4];
            wp[0] = *(const ull*)&wv0.x; wp[1] = *(const ull*)&wv0.z;
            wp[2] = *(const ull*)&wv1.x; wp[3] = *(const ull*)&wv1.z;
            ull hd0 = dup2(h0[k]);
            ull hd1 = dup2(has2 ? h1p[k] : 0.f);
#pragma unroll
            for (int i = 0; i < 4; i++) { ffma2(a0[i], hd0, wp[i]); ffma2(a1[i], hd1, wp[i]); }
        }

        float m[8];
#pragma unroll
        for (int i = 0; i < 4; i++) {
            float bx = b2[w * 8 + 2 * i], by = b2[w * 8 + 2 * i + 1];
            float2 p0 = unpk2(a0[i]);
            float2 p1 = unpk2(a1[i]);
            float v0x = lrelu(p0.x + bx), v0y = lrelu(p0.y + by);
            float v1x = has2 ? lrelu(p1.x + bx) : -3.4e38f;
            float v1y = has2 ? lrelu(p1.y + by) : -3.4e38f;
            m[2 * i] = fmaxf(v0x, v1x);
            m[2 * i + 1] = fmaxf(v0y, v1y);
        }
#pragma unroll
        for (int o = 16; o > 0; o >>= 1)
#pragma unroll
            for (int i = 0; i < 8; i++) m[i] = fmaxf(m[i], __shfl_down_sync(0xffffffffu, m[i], o));
        if (lane == 0) {
#pragma unroll
            for (int i = 0; i < 8; i++)
                g_dnfeat[(size_t)(b * DNOUT + w * 8 + i) * NPT + ni] = m[i];
        }
        __syncthreads();   // H reused next point
    }
}

// ---------------- sparse GCN (k=2 over 32 strokes) ----------------
__global__ void __launch_bounds__(192) k_sparse(const float* __restrict__ W1, const float* __restrict__ b1,
                                                const float* __restrict__ W2, const float* __restrict__ b2,
                                                float* __restrict__ out) {
    int bi = blockIdx.x;
    int b = bi >> 5, i = bi & 31;
    __shared__ float xi[CIN];
    __shared__ float d[NSTK];
    __shared__ float h1[MIDSP];
    __shared__ int nbr2[2];
    const float* Xs = g_xs + b * NSTK * CIN;
    int t = threadIdx.x;
    if (t < CIN) xi[t] = Xs[i * CIN + t];
    __syncthreads();
    if (t < NSTK) {
        float s = 0.f;
        for (int cc = 0; cc < CIN; cc++) { float dx = Xs[t * CIN + cc] - xi[cc]; s += dx * dx; }
        d[t] = s;
    }
    __syncthreads();
    if (t == 0) {
        int i1 = 0; float v1 = d[0];
        for (int j = 1; j < NSTK; j++) if (d[j] < v1) { v1 = d[j]; i1 = j; }
        int i2 = -1; float v2 = 3.4e38f;
        for (int j = 0; j < NSTK; j++) { if (j == i1) continue; if (d[j] < v2) { v2 = d[j]; i2 = j; } }
        nbr2[0] = i1; nbr2[1] = i2;
    }
    __syncthreads();
    float acc = -3.4e38f;
    for (int jj = 0; jj < 2; jj++) {
        int nb = nbr2[jj];
        __syncthreads();
        if (t < MIDSP) {
            float s = b1[t];
            const float* w = W1 + t * (2 * CIN);
            for (int cc = 0; cc < CIN; cc++) {
                float xj = Xs[nb * CIN + cc], xc = xi[cc];
                s += (xj - xc) * w[cc] + xc * w[CIN + cc];
            }
            h1[t] = lrelu(s);
        }
        __syncthreads();
        if (t < SPOUT) {
            float s = b2[t];
            const float* w = W2 + t * MIDSP;
            for (int k = 0; k < MIDSP; k++) s += w[k] * h1[k];
            acc = fmaxf(acc, lrelu(s));
        }
    }
    if (t < SPOUT) out[(b * SPOUT + t) * NSTK + i] = acc;
}

// ---------------- downsample conv (1,3)/stride(1,2)/pad(0,1) + leaky ----------------
__global__ void __launch_bounds__(256) k_down(const float* __restrict__ dsW, const float* __restrict__ dsb,
                                              float* __restrict__ out) {
    extern __shared__ float sm[];
    float* tile = sm;                 // [64][256]
    float* Wsh = sm + DNOUT * NPNT;   // [64][64][3]
    int bs_ = blockIdx.x;
    int b = bs_ >> 5, s = bs_ & 31;
    int t = threadIdx.x;
    for (int idx = t; idx < DNOUT * NPNT; idx += 256) {
        int ic = idx >> 8, p = idx & 255;
        tile[idx] = g_dnfeat[(size_t)(b * DNOUT + ic) * NPT + s * NPNT + p];
    }
    for (int idx = t; idx < DNOUT * DNOUT * 3; idx += 256) Wsh[idx] = dsW[idx];
    __syncthreads();
    const int QO = NPNT / 2;          // 128
    for (int idx = t; idx < DNOUT * QO; idx += 256) {
        int o = idx >> 7, q = idx & 127;
        float acc = dsb[o];
        int pbase = 2 * q - 1;
        const float* wrow = Wsh + o * (DNOUT * 3);
        for (int ic = 0; ic < DNOUT; ic++) {
            const float* tr = tile + ic * NPNT;
            float w0 = wrow[ic * 3 + 0], w1 = wrow[ic * 3 + 1], w2 = wrow[ic * 3 + 2];
            float a = 0.f;
            if (pbase >= 0) a += tr[pbase] * w0;
            a += tr[pbase + 1] * w1;
            if (pbase + 2 < NPNT) a += tr[pbase + 2] * w2;
            acc += a;
        }
        out[BS * SPOUT * NSTK + (((size_t)b * DNOUT + o) * NSTK + s) * QO + q] = lrelu(acc);
    }
}

extern "C" void kernel_launch(void* const* d_in, const int* in_sizes, int n_in,
                              void* d_out, int out_size) {
    const float* sparse = (const float*)d_in[0];
    const float* dense  = (const float*)d_in[1];
    const float* spW1 = (const float*)d_in[2];
    const float* spb1 = (const float*)d_in[3];
    const float* spW2 = (const float*)d_in[4];
    const float* spb2 = (const float*)d_in[5];
    const float* dnW1 = (const float*)d_in[6];
    const float* dnb1 = (const float*)d_in[7];
    const float* dnW2 = (const float*)d_in[8];
    const float* dnb2 = (const float*)d_in[9];
    const float* dsW  = (const float*)d_in[10];
    const float* dsb  = (const float*)d_in[11];
    float* out = (float*)d_out;

    const int AB_SMEM   = (2 * MIDDN * ABPITCH + 16 * CIN) * 4;                      // ~91.5 KB
    const int MLP_SMEM  = (MIDDN * 64 + KDN * HP + 8 * 112) * 4 + 8 * KDN * 4;       // ~55.9 KB
    const int DOWN_SMEM = (DNOUT * NPNT + DNOUT * DNOUT * 3) * 4;                    // 112 KB
    cudaFuncSetAttribute(k_AB,   cudaFuncAttributeMaxDynamicSharedMemorySize, AB_SMEM);
    cudaFuncSetAttribute(k_mlp,  cudaFuncAttributeMaxDynamicSharedMemorySize, MLP_SMEM);
    cudaFuncSetAttribute(k_down, cudaFuncAttributeMaxDynamicSharedMemorySize, DOWN_SMEM);

    // Launch order: k_topk stays the 4th launch so ncu's capture window profiles it.
    k_build_xt<<<BS * NPT, CIN>>>(dense, sparse);
    k_dist<<<dim3(NPT / 128, NPT / 128, BS), 256>>>();
    k_spdn<<<BS * DNIN * NSTK, 256>>>(dense);
    k_topk<<<BS * NPT, 256>>>();
    k_xs_sp<<<BS * NSTK, SPIN>>>(sparse);
    k_AB<<<(BS * NPT) / 16, 256, AB_SMEM>>>(dnW1, dnb1);
    k_mlp<<<(BS * NPT) / 8, 256, MLP_SMEM>>>(dnW2, dnb2);
    k_sparse<<<BS * NSTK, 192>>>(spW1, spb1, spW2, spb2, out);
    k_down<<<BS * NSTK, 256, DOWN_SMEM>>>(dsW, dsb, out);
}

// round 17
// speedup vs baseline: 1.1496x; 1.0013x over previous
#include <cuda_runtime.h>
#include <cuda_bf16.h>
#include <cstddef>

#define LEAK 0.2f
#define BS 4
#define NSTK 32
#define NPNT 256
#define NPT 8192           // NSTK*NPNT
#define CIN 96
#define SPIN 64
#define DNIN 32
#define MIDDN 110
#define DNOUT 64
#define MIDSP 156
#define SPOUT 128
#define KDN 50

typedef unsigned long long ull;

// ---------------- scratch (allocation-free rule: __device__ globals) ----------------
__device__ float g_xt[(size_t)BS * NPT * CIN];       // point-major fused dense features
__device__ float g_x2[BS * NPT];
__device__ unsigned g_D[(size_t)BS * NPT * NPT];     // 1 GiB ORDERING KEYS (okey of distance)
__device__ int   g_knn[(size_t)BS * NPT * KDN];
__device__ float g_A[(size_t)BS * NPT * MIDDN];      // x @ W1a^T
__device__ float g_B[(size_t)BS * NPT * MIDDN];      // x @ (W1b-W1a)^T + b1
__device__ float g_dnfeat[(size_t)BS * DNOUT * NPT]; // channel-major GCN output
__device__ float g_xs[BS * NSTK * CIN];              // fused sparse features, point-major

__device__ __forceinline__ float lrelu(float v) { return v > 0.f ? v : LEAK * v; }

// packed f32x2 helpers (FFMA2 on sm_103a: saves issue slots vs 2x FFMA)
__device__ __forceinline__ ull dup2(float x) { ull r; asm("mov.b64 %0,{%1,%1};" : "=l"(r) : "f"(x)); return r; }
__device__ __forceinline__ void ffma2(ull& d, ull a, ull b) {
    asm("fma.rn.f32x2 %0,%1,%2,%0;" : "+l"(d) : "l"(a), "l"(b));
}
__device__ __forceinline__ float2 unpk2(ull v) { float2 f; asm("mov.b64 {%0,%1},%2;" : "=f"(f.x), "=f"(f.y) : "l"(v)); return f; }

__device__ __forceinline__ unsigned okey(float d) {
    unsigned u = __float_as_uint(d);
    return (u & 0x80000000u) ? ~u : (u | 0x80000000u);
}

// ---------------- build fused dense features + squared norms ----------------
__global__ void k_build_xt(const float* __restrict__ dense, const float* __restrict__ sparse) {
    int bn = blockIdx.x;            // b*NPT + n
    int b = bn >> 13, n = bn & (NPT - 1);
    int s = n >> 8, p = n & 255;
    int t = threadIdx.x;            // 96
    float v;
    if (t < DNIN) v = dense[(((size_t)(b * DNIN + t) * NSTK + s) << 8) + p];
    else          v = sparse[(b * SPIN + (t - DNIN)) * NSTK + s];
    g_xt[(size_t)bn * CIN + t] = v;
    __shared__ float red[CIN];
    red[t] = v * v;
    __syncthreads();
    if (t < 32) {
        float s2 = red[t] + red[t + 32] + red[t + 64];
        for (int o = 16; o > 0; o >>= 1) s2 += __shfl_down_sync(0xffffffffu, s2, o);
        if (t == 0) g_x2[bn] = s2;
    }
}

// ---------------- sparse fused features ----------------
__global__ void k_spdn(const float* __restrict__ dense) {
    int idx = blockIdx.x;           // (b, c, s)
    int b = idx >> 10, c = (idx >> 5) & 31, s = idx & 31;
    int t = threadIdx.x;            // 256
    float v = dense[(((size_t)(b * DNIN + c) * NSTK + s) << 8) + t];
    __shared__ float red[256];
    red[t] = v;
    __syncthreads();
    for (int o = 128; o >= 32; o >>= 1) { if (t < o) red[t] = fmaxf(red[t], red[t + o]); __syncthreads(); }
    if (t < 32) {
        float m = red[t];
        for (int o = 16; o > 0; o >>= 1) m = fmaxf(m, __shfl_down_sync(0xffffffffu, m, o));
        if (t == 0) g_xs[(b * NSTK + s) * CIN + SPIN + c] = m;
    }
}
__global__ void k_xs_sp(const float* __restrict__ sparse) {
    int bs_ = blockIdx.x;
    int b = bs_ >> 5, s = bs_ & 31;
    int t = threadIdx.x;            // 64
    g_xs[(b * NSTK + s) * CIN + t] = sparse[(b * SPIN + t) * NSTK + s];
}

// ---------------- pairwise distances: 128x128 tile, 8x8 microtile, FFMA2, double-buffered ----------------
// Stores okey(distance) so k_topk needs no conversion.
#define DPITCH 132
__global__ void __launch_bounds__(256, 2) k_dist() {
    int bx = blockIdx.x, by = blockIdx.y;   // j-tile, i-tile
    if (by > bx) return;                    // symmetry: only upper-tri tile grid
    int b = blockIdx.z;
    int i0 = by * 128, j0 = bx * 128;
    const float* X = g_xt + (size_t)b * NPT * CIN;
    const float* x2 = g_x2 + b * NPT;
    __shared__ float As[2][16][DPITCH];
    __shared__ float Bs[2][16][DPITCH];
    int t = threadIdx.x;
    int tx = t & 15, ty = t >> 4;

    ull acc[4][8];
#pragma unroll
    for (int u = 0; u < 4; u++)
#pragma unroll
        for (int v = 0; v < 8; v++) acc[u][v] = 0ULL;

    int lr = t >> 2, kq = t & 3;
    const float* Abase = X + (size_t)(i0 + lr) * CIN + kq * 4;
    const float* Bbase = X + (size_t)(j0 + lr) * CIN + kq * 4;
    float4 pa0 = *(const float4*)(Abase);
    float4 pa1 = *(const float4*)(Abase + (size_t)64 * CIN);
    float4 pb0 = *(const float4*)(Bbase);
    float4 pb1 = *(const float4*)(Bbase + (size_t)64 * CIN);

    int kb = kq * 4;
    for (int c = 0; c < 6; c++) {
        int p = c & 1;
        As[p][kb + 0][lr] = pa0.x; As[p][kb + 1][lr] = pa0.y; As[p][kb + 2][lr] = pa0.z; As[p][kb + 3][lr] = pa0.w;
        As[p][kb + 0][lr + 64] = pa1.x; As[p][kb + 1][lr + 64] = pa1.y; As[p][kb + 2][lr + 64] = pa1.z; As[p][kb + 3][lr + 64] = pa1.w;
        Bs[p][kb + 0][lr] = pb0.x; Bs[p][kb + 1][lr] = pb0.y; Bs[p][kb + 2][lr] = pb0.z; Bs[p][kb + 3][lr] = pb0.w;
        Bs[p][kb + 0][lr + 64] = pb1.x; Bs[p][kb + 1][lr + 64] = pb1.y; Bs[p][kb + 2][lr + 64] = pb1.z; Bs[p][kb + 3][lr + 64] = pb1.w;
        __syncthreads();
        if (c < 5) {
            int ko = (c + 1) * 16;
            pa0 = *(const float4*)(Abase + ko);
            pa1 = *(const float4*)(Abase + (size_t)64 * CIN + ko);
            pb0 = *(const float4*)(Bbase + ko);
            pb1 = *(const float4*)(Bbase + (size_t)64 * CIN + ko);
        }
#pragma unroll
        for (int k = 0; k < 16; k++) {
            ull a[4];
#pragma unroll
            for (int u = 0; u < 4; u++) a[u] = *(const ull*)&As[p][k][ty * 8 + u * 2];
            float4 q0 = *(const float4*)&Bs[p][k][tx * 8];
            float4 q1 = *(const float4*)&Bs[p][k][tx * 8 + 4];
            ull bd[8];
            bd[0] = dup2(q0.x); bd[1] = dup2(q0.y); bd[2] = dup2(q0.z); bd[3] = dup2(q0.w);
            bd[4] = dup2(q1.x); bd[5] = dup2(q1.y); bd[6] = dup2(q1.z); bd[7] = dup2(q1.w);
#pragma unroll
            for (int u = 0; u < 4; u++)
#pragma unroll
                for (int v = 0; v < 8; v++) ffma2(acc[u][v], a[u], bd[v]);
        }
    }

    float x2i[8], x2j[8];
#pragma unroll
    for (int u = 0; u < 8; u++) x2i[u] = x2[i0 + ty * 8 + u];
#pragma unroll
    for (int v = 0; v < 8; v++) x2j[v] = x2[j0 + tx * 8 + v];
    unsigned d[8][8];
#pragma unroll
    for (int u = 0; u < 4; u++)
#pragma unroll
        for (int v = 0; v < 8; v++) {
            float2 p2 = unpk2(acc[u][v]);
            d[2 * u + 0][v] = okey(x2i[2 * u + 0] + x2j[v] - 2.f * p2.x);
            d[2 * u + 1][v] = okey(x2i[2 * u + 1] + x2j[v] - 2.f * p2.y);
        }
    unsigned* Dp = g_D + (size_t)b * NPT * NPT;
#pragma unroll
    for (int u = 0; u < 8; u++) {
        size_t r = (size_t)(i0 + ty * 8 + u) * NPT + j0 + tx * 8;
        uint4 w0 = make_uint4(d[u][0], d[u][1], d[u][2], d[u][3]);
        uint4 w1 = make_uint4(d[u][4], d[u][5], d[u][6], d[u][7]);
        *(uint4*)&Dp[r] = w0;
        *(uint4*)&Dp[r + 4] = w1;
    }
    if (bx != by) {
#pragma unroll
        for (int v = 0; v < 8; v++) {
            size_t r = (size_t)(j0 + tx * 8 + v) * NPT + i0 + ty * 8;
            uint4 m0 = make_uint4(d[0][v], d[1][v], d[2][v], d[3][v]);
            uint4 m1 = make_uint4(d[4][v], d[5][v], d[6][v], d[7][v]);
            *(uint4*)&Dp[r] = m0;
            *(uint4*)&Dp[r + 4] = m1;
        }
    }
}

// ---------------- top-50 per row v10: 128-sample stratified threshold (split rank count) ----------------
__global__ void __launch_bounds__(256, 8) k_topk() {
    int row = blockIdx.x;
    const unsigned* K = g_D + (size_t)row * NPT;
    const uint4* K4 = (const uint4*)K;
    __shared__ unsigned samp[128];
    __shared__ int rcnt[128];
    __shared__ unsigned sh_T[2];
    __shared__ int hist[1024];
    __shared__ unsigned ckey[1024];
    __shared__ int cidx[1024];
    __shared__ int wsum[8];
    __shared__ unsigned sh_pref;
    __shared__ int sh_kk, sh_cless, sh_tiecnt, sh_cc;
    __shared__ int tielist[256];
    int t = threadIdx.x, lane = t & 31, w = t >> 5;

    if (t < 128) { samp[t] = K[t << 6]; rcnt[t] = 0; }   // stratified: every 64th key
    if (t < 2) sh_T[t] = 0u;
    __syncthreads();

    // split rank count: thread handles sample (t&127) against half the sample set
    {
        int s = t & 127;
        unsigned v = samp[s];
        int base = (t >> 7) * 64;
        int cnt = 0;
#pragma unroll 8
        for (int j = 0; j < 64; j++) cnt += (samp[base + j] < v) ? 1 : 0;
        atomicAdd(&rcnt[s], cnt);
    }
    __syncthreads();
    if (t < 128) {
        int cnt = rcnt[t];
        unsigned v = samp[t];
        if (cnt < 4)  atomicMax(&sh_T[0], v);   // ~rank-4 of 128  -> E[c] ~ 256
        if (cnt < 12) atomicMax(&sh_T[1], v);   // ~rank-12 of 128 -> E[c] ~ 768
    }
    __syncthreads();

    // streaming count + compact; accept only if count is verifiably in range
    int c = 0;
    bool ok = false;
    for (int level = 0; level < 2; level++) {
        if (t == 0) sh_cc = 0;
        __syncthreads();
        unsigned T = sh_T[level];
        for (int i = t; i < NPT / 4; i += 256) {
            uint4 kv = K4[i];               // default caching: retries hit L2
            bool m0 = kv.x <= T, m1 = kv.y <= T, m2 = kv.z <= T, m3 = kv.w <= T;
            if (m0 | m1 | m2 | m3) {
                int j = 4 * i;
                if (m0) { int p = atomicAdd(&sh_cc, 1); if (p < 1024) { ckey[p] = kv.x; cidx[p] = j; } }
                if (m1) { int p = atomicAdd(&sh_cc, 1); if (p < 1024) { ckey[p] = kv.y; cidx[p] = j + 1; } }
                if (m2) { int p = atomicAdd(&sh_cc, 1); if (p < 1024) { ckey[p] = kv.z; cidx[p] = j + 2; } }
                if (m3) { int p = atomicAdd(&sh_cc, 1); if (p < 1024) { ckey[p] = kv.w; cidx[p] = j + 3; } }
            }
        }
        __syncthreads();
        c = sh_cc;                          // exact count of {key <= T}
        __syncthreads();                    // protect sh_cc reset next iteration
        if (c >= KDN && c <= 1024) { ok = true; break; }
        if (c > 1024) break;                // larger thresholds only worse -> exact fallback
    }
    int m = c < 1024 ? c : 1024;

    // exact radix select (widths 10,8,7,7) for the KDN-th smallest
    // over candidates (ok) or the full row from gmem (fallback; always exact)
    if (t == 0) { sh_kk = KDN; sh_cless = 0; sh_tiecnt = 0; }
    __syncthreads();
    unsigned pref = 0u;
    const int widths[4] = {10, 8, 7, 7};
    const int shifts[4] = {22, 14, 7, 0};
    for (int pass = 0; pass < 4; ++pass) {
        int shift = shifts[pass], wd = widths[pass];
        unsigned msk = (1u << wd) - 1u;
        int nb = 1 << wd;
        for (int i = t; i < nb; i += 256) hist[i] = 0;
        __syncthreads();
        if (ok) {
            for (int ci = t; ci < m; ci += 256) {
                unsigned kx = ckey[ci];
                if (pass == 0 || (kx >> (shift + wd)) == pref) atomicAdd(&hist[(kx >> shift) & msk], 1);
            }
        } else {
            for (int j = t; j < NPT; j += 256) {
                unsigned kx = K[j];
                if (pass == 0 || (kx >> (shift + wd)) == pref) atomicAdd(&hist[(kx >> shift) & msk], 1);
            }
        }
        __syncthreads();
        if (nb == 1024) {
            int base = t * 4;
            int s4 = hist[base] + hist[base + 1] + hist[base + 2] + hist[base + 3];
            int incl = s4;
#pragma unroll
            for (int o = 1; o < 32; o <<= 1) { int v = __shfl_up_sync(0xffffffffu, incl, o); if (lane >= o) incl += v; }
            if (lane == 31) wsum[w] = incl;
            __syncthreads();
            if (t < 8) {
                int v = wsum[t];
#pragma unroll
                for (int o = 1; o < 8; o <<= 1) { int u2 = __shfl_up_sync(0xffu, v, o); if (t >= o) v += u2; }
                wsum[t] = v;
            }
            __syncthreads();
            int incl2 = incl + ((w > 0) ? wsum[w - 1] : 0);
            int excl = incl2 - s4;
            int kk = sh_kk;
            __syncthreads();
            if (kk > excl && kk <= incl2) {
                int cc = excl;
#pragma unroll
                for (int i = 0; i < 4; i++) {
                    int h = hist[base + i];
                    if (cc + h >= kk) { sh_pref = (unsigned)(base + i); sh_kk = kk - cc; break; }
                    cc += h;
                }
            }
        } else {
            int h = (t < nb) ? hist[t] : 0;
            int inc = h;
#pragma unroll
            for (int o = 1; o < 32; o <<= 1) { int v = __shfl_up_sync(0xffffffffu, inc, o); if (lane >= o) inc += v; }
            if (lane == 31) wsum[w] = inc;
            __syncthreads();
            int wadd = 0;
            if (t < nb) { for (int ww = 0; ww < (t >> 5); ww++) wadd += wsum[ww]; }
            int inc2 = inc + wadd;
            int exc = inc2 - h;
            int kk = sh_kk;
            __syncthreads();
            if (t < nb && kk > exc && kk <= inc2) { sh_pref = (pref << wd) | (unsigned)t; sh_kk = kk - exc; }
        }
        __syncthreads();
        pref = sh_pref;
    }

    unsigned T = pref;              // exact 32-bit key of the KDN-th smallest
    int* outp = g_knn + (size_t)row * KDN;
    if (ok) {
        for (int ci = t; ci < m; ci += 256) {
            unsigned kx = ckey[ci];
            if (kx < T) { int pos = atomicAdd(&sh_cless, 1); outp[pos] = cidx[ci]; }
            else if (kx == T) { int p = atomicAdd(&sh_tiecnt, 1); if (p < 256) tielist[p] = cidx[ci]; }
        }
    } else {
        for (int j = t; j < NPT; j += 256) {
            unsigned kx = K[j];
            if (kx < T) { int pos = atomicAdd(&sh_cless, 1); outp[pos] = j; }
            else if (kx == T) { int p = atomicAdd(&sh_tiecnt, 1); if (p < 256) tielist[p] = j; }
        }
    }
    __syncthreads();
    if (t == 0) {
        int cl = sh_cless, need = KDN - cl;
        int mm = sh_tiecnt < 256 ? sh_tiecnt : 256;
        for (int a = 1; a < mm; a++) {          // ascending index = jax stable tie-break
            int v = tielist[a], bdx = a - 1;
            while (bdx >= 0 && tielist[bdx] > v) { tielist[bdx + 1] = tielist[bdx]; bdx--; }
            tielist[bdx + 1] = v;
        }
        for (int a = 0; a < need; a++) outp[cl + a] = tielist[a];
    }
}

// ---------------- A = x@W1a^T ; B = x@(W1b-W1a)^T + b1 (layer-1 factorization) ----------------
#define ABPITCH 97
__global__ void __launch_bounds__(256) k_AB(const float* __restrict__ W1, const float* __restrict__ b1) {
    extern __shared__ float sm[];
    float* Wa = sm;                           // [110][97]
    float* Wd = sm + MIDDN * ABPITCH;         // [110][97]
    float* xs = sm + 2 * MIDDN * ABPITCH;     // [16][96]
    int t = threadIdx.x;
    for (int idx = t; idx < MIDDN * CIN; idx += 256) {
        int k = idx / CIN, c = idx % CIN;
        float wa = W1[k * (2 * CIN) + c];
        float wb = W1[k * (2 * CIN) + CIN + c];
        Wa[k * ABPITCH + c] = wa;
        Wd[k * ABPITCH + c] = wb - wa;
    }
    int p0 = blockIdx.x * 16;
    for (int idx = t; idx < 16 * CIN; idx += 256)
        xs[idx] = g_xt[(size_t)(p0 + idx / CIN) * CIN + (idx % CIN)];
    __syncthreads();
    for (int idx = t; idx < 16 * MIDDN; idx += 256) {
        int pp = idx / MIDDN, k = idx % MIDDN;
        const float* xr = xs + pp * CIN;
        float a = 0.f, bb = 0.f;
#pragma unroll
        for (int c = 0; c < CIN; c++) {
            float xv = xr[c];
            a += xv * Wa[k * ABPITCH + c];
            bb += xv * Wd[k * ABPITCH + c];
        }
        size_t off = (size_t)(p0 + pp) * MIDDN + k;
        g_A[off] = a;
        g_B[off] = bb + b1[k];
    }
}

// ---------------- per-point edge MLP v4: 8 points/block, W2t staged once ----------------
#define HP 113   // pitch: (113*j + k) % 32 = (17j + k) % 32, 17 odd -> conflict-free across lanes
__global__ void __launch_bounds__(256) k_mlp(const float* __restrict__ W2, const float* __restrict__ b2) {
    extern __shared__ float dsm[];
    float* W2t = dsm;                         // [110][64]
    float* H   = dsm + MIDDN * 64;            // [50][113]
    float* Bp8 = H + KDN * HP;                // [8][112]
    int*  nbrs8 = (int*)(Bp8 + 8 * 112);      // [8][50]
    int t = threadIdx.x, lane = t & 31, w = t >> 5;
    int n0 = blockIdx.x * 8;

    for (int idx = t; idx < MIDDN * 64; idx += 256) {
        int k = idx >> 6, c = idx & 63;
        W2t[idx] = W2[c * MIDDN + k];
    }
    for (int idx = t; idx < 8 * MIDDN; idx += 256) {
        int pi = idx / MIDDN, k = idx - pi * MIDDN;
        Bp8[pi * 112 + k] = g_B[(size_t)(n0 + pi) * MIDDN + k];
    }
    for (int idx = t; idx < 8 * KDN; idx += 256) {
        int pi = idx / KDN, j = idx - pi * KDN;
        nbrs8[pi * KDN + j] = g_knn[(size_t)(n0 + pi) * KDN + j];
    }
    __syncthreads();

    for (int pi = 0; pi < 8; ++pi) {
        int n = n0 + pi, b = n >> 13, ni = n & (NPT - 1);
        const float* Bp = Bp8 + pi * 112;
        const int* nbrs = nbrs8 + pi * KDN;
        for (int idx = t; idx < KDN * MIDDN; idx += 256) {
            int j = idx / MIDDN, k = idx - j * MIDDN;
            H[j * HP + k] = lrelu(g_A[(size_t)(b * NPT + nbrs[j]) * MIDDN + k] + Bp[k]);
        }
        __syncthreads();

        bool has2 = (lane + 32) < KDN;
        const float* h0 = H + lane * HP;
        const float* h1p = H + (lane + 32) * HP;
        ull a0[4], a1[4];
#pragma unroll
        for (int i = 0; i < 4; i++) { a0[i] = 0ULL; a1[i] = 0ULL; }
        const float* Wb = W2t + w * 8;
        for (int k = 0; k < MIDDN; k++) {
            float4 wv0 = *(const float4*)&Wb[k * 64];      // broadcast within warp
            float4 wv1 = *(const float4*)&Wb[k * 64 + 4];
            ull wp[4];
            wp[0] = *(const ull*)&wv0.x; wp[1] = *(const ull*)&wv0.z;
            wp[2] = *(const ull*)&wv1.x; wp[3] = *(const ull*)&wv1.z;
            ull hd0 = dup2(h0[k]);
            ull hd1 = dup2(has2 ? h1p[k] : 0.f);
#pragma unroll
            for (int i = 0; i < 4; i++) { ffma2(a0[i], hd0, wp[i]); ffma2(a1[i], hd1, wp[i]); }
        }

        float m[8];
#pragma unroll
        for (int i = 0; i < 4; i++) {
            float bx = b2[w * 8 + 2 * i], by = b2[w * 8 + 2 * i + 1];
            float2 p0 = unpk2(a0[i]);
            float2 p1 = unpk2(a1[i]);
            float v0x = lrelu(p0.x + bx), v0y = lrelu(p0.y + by);
            float v1x = has2 ? lrelu(p1.x + bx) : -3.4e38f;
            float v1y = has2 ? lrelu(p1.y + by) : -3.4e38f;
            m[2 * i] = fmaxf(v0x, v1x);
            m[2 * i + 1] = fmaxf(v0y, v1y);
        }
#pragma unroll
        for (int o = 16; o > 0; o >>= 1)
#pragma unroll
            for (int i = 0; i < 8; i++) m[i] = fmaxf(m[i], __shfl_down_sync(0xffffffffu, m[i], o));
        if (lane == 0) {
#pragma unroll
            for (int i = 0; i < 8; i++)
                g_dnfeat[(size_t)(b * DNOUT + w * 8 + i) * NPT + ni] = m[i];
        }
        __syncthreads();   // H reused next point
    }
}

// ---------------- sparse GCN (k=2 over 32 strokes) ----------------
__global__ void __launch_bounds__(192) k_sparse(const float* __restrict__ W1, const float* __restrict__ b1,
                                                const float* __restrict__ W2, const float* __restrict__ b2,
                                                float* __restrict__ out) {
    int bi = blockIdx.x;
    int b = bi >> 5, i = bi & 31;
    __shared__ float xi[CIN];
    __shared__ float d[NSTK];
    __shared__ float h1[MIDSP];
    __shared__ int nbr2[2];
    const float* Xs = g_xs + b * NSTK * CIN;
    int t = threadIdx.x;
    if (t < CIN) xi[t] = Xs[i * CIN + t];
    __syncthreads();
    if (t < NSTK) {
        float s = 0.f;
        for (int cc = 0; cc < CIN; cc++) { float dx = Xs[t * CIN + cc] - xi[cc]; s += dx * dx; }
        d[t] = s;
    }
    __syncthreads();
    if (t == 0) {
        int i1 = 0; float v1 = d[0];
        for (int j = 1; j < NSTK; j++) if (d[j] < v1) { v1 = d[j]; i1 = j; }
        int i2 = -1; float v2 = 3.4e38f;
        for (int j = 0; j < NSTK; j++) { if (j == i1) continue; if (d[j] < v2) { v2 = d[j]; i2 = j; } }
        nbr2[0] = i1; nbr2[1] = i2;
    }
    __syncthreads();
    float acc = -3.4e38f;
    for (int jj = 0; jj < 2; jj++) {
        int nb = nbr2[jj];
        __syncthreads();
        if (t < MIDSP) {
            float s = b1[t];
            const float* w = W1 + t * (2 * CIN);
            for (int cc = 0; cc < CIN; cc++) {
                float xj = Xs[nb * CIN + cc], xc = xi[cc];
                s += (xj - xc) * w[cc] + xc * w[CIN + cc];
            }
            h1[t] = lrelu(s);
        }
        __syncthreads();
        if (t < SPOUT) {
            float s = b2[t];
            const float* w = W2 + t * MIDSP;
            for (int k = 0; k < MIDSP; k++) s += w[k] * h1[k];
            acc = fmaxf(acc, lrelu(s));
        }
    }
    if (t < SPOUT) out[(b * SPOUT + t) * NSTK + i] = acc;
}

// ---------------- downsample conv (1,3)/stride(1,2)/pad(0,1) + leaky ----------------
__global__ void __launch_bounds__(256) k_down(const float* __restrict__ dsW, const float* __restrict__ dsb,
                                              float* __restrict__ out) {
    extern __shared__ float sm[];
    float* tile = sm;                 // [64][256]
    float* Wsh = sm + DNOUT * NPNT;   // [64][64][3]
    int bs_ = blockIdx.x;
    int b = bs_ >> 5, s = bs_ & 31;
    int t = threadIdx.x;
    for (int idx = t; idx < DNOUT * NPNT; idx += 256) {
        int ic = idx >> 8, p = idx & 255;
        tile[idx] = g_dnfeat[(size_t)(b * DNOUT + ic) * NPT + s * NPNT + p];
    }
    for (int idx = t; idx < DNOUT * DNOUT * 3; idx += 256) Wsh[idx] = dsW[idx];
    __syncthreads();
    const int QO = NPNT / 2;          // 128
    for (int idx = t; idx < DNOUT * QO; idx += 256) {
        int o = idx >> 7, q = idx & 127;
        float acc = dsb[o];
        int pbase = 2 * q - 1;
        const float* wrow = Wsh + o * (DNOUT * 3);
        for (int ic = 0; ic < DNOUT; ic++) {
            const float* tr = tile + ic * NPNT;
            float w0 = wrow[ic * 3 + 0], w1 = wrow[ic * 3 + 1], w2 = wrow[ic * 3 + 2];
            float a = 0.f;
            if (pbase >= 0) a += tr[pbase] * w0;
            a += tr[pbase + 1] * w1;
            if (pbase + 2 < NPNT) a += tr[pbase + 2] * w2;
            acc += a;
        }
        out[BS * SPOUT * NSTK + (((size_t)b * DNOUT + o) * NSTK + s) * QO + q] = lrelu(acc);
    }
}

extern "C" void kernel_launch(void* const* d_in, const int* in_sizes, int n_in,
                              void* d_out, int out_size) {
    const float* sparse = (const float*)d_in[0];
    const float* dense  = (const float*)d_in[1];
    const float* spW1 = (const float*)d_in[2];
    const float* spb1 = (const float*)d_in[3];
    const float* spW2 = (const float*)d_in[4];
    const float* spb2 = (const float*)d_in[5];
    const float* dnW1 = (const float*)d_in[6];
    const float* dnb1 = (const float*)d_in[7];
    const float* dnW2 = (const float*)d_in[8];
    const float* dnb2 = (const float*)d_in[9];
    const float* dsW  = (const float*)d_in[10];
    const float* dsb  = (const float*)d_in[11];
    float* out = (float*)d_out;

    const int AB_SMEM   = (2 * MIDDN * ABPITCH + 16 * CIN) * 4;                      // ~91.5 KB
    const int MLP_SMEM  = (MIDDN * 64 + KDN * HP + 8 * 112) * 4 + 8 * KDN * 4;       // ~55.9 KB
    const int DOWN_SMEM = (DNOUT * NPNT + DNOUT * DNOUT * 3) * 4;                    // 112 KB
    cudaFuncSetAttribute(k_AB,   cudaFuncAttributeMaxDynamicSharedMemorySize, AB_SMEM);
    cudaFuncSetAttribute(k_mlp,  cudaFuncAttributeMaxDynamicSharedMemorySize, MLP_SMEM);
    cudaFuncSetAttribute(k_down, cudaFuncAttributeMaxDynamicSharedMemorySize, DOWN_SMEM);

    // Launch order: k_topk stays the 4th launch so ncu's capture window profiles it.
    k_build_xt<<<BS * NPT, CIN>>>(dense, sparse);
    k_dist<<<dim3(NPT / 128, NPT / 128, BS), 256>>>();
    k_spdn<<<BS * DNIN * NSTK, 256>>>(dense);
    k_topk<<<BS * NPT, 256>>>();
    k_xs_sp<<<BS * NSTK, SPIN>>>(sparse);
    k_AB<<<(BS * NPT) / 16, 256, AB_SMEM>>>(dnW1, dnb1);
    k_mlp<<<(BS * NPT) / 8, 256, MLP_SMEM>>>(dnW2, dnb2);
    k_sparse<<<BS * NSTK, 192>>>(spW1, spb1, spW2, spb2, out);
    k_down<<<BS * NSTK, 256, DOWN_SMEM>>>(dsW, dsb, out);
}